// round 5
// baseline (speedup 1.0000x reference)
#include <cuda_runtime.h>
#include <cuda_bf16.h>

// Problem constants
#define NLAY 3
#define BB   2
#define LS   1024
#define ES   1024
#define HH   16
#define DH   64
#define MROWS (BB*LS)              // 2048
#define LAYER_ELEMS (BB*LS*ES)     // 2097152
#define ATT_SCALE 0.125f           // D^-0.5 = 1/8
#define EPSF 1e-5f

// ---------------- scratch (static device allocations; no cudaMalloc) --------
__device__ float d_QB[NLAY * LAYER_ELEMS];
__device__ float d_KB[NLAY * LAYER_ELEMS];
__device__ float d_VB[NLAY * LAYER_ELEMS];
__device__ float d_AB[NLAY * LAYER_ELEMS];
__device__ float d_YB[LAYER_ELEMS];

// ---------------- SGEMM: C = A @ B^T ----------------------------------------
// A: M x K row-major, Bmat: N x K row-major, C: M x K... C: M x N row-major.
// Grid: (N/128, M/128, Z). blockIdx.z selects Bmat + z*strideB, C + z*strideC.
#define BMT 128
#define BNT 128
#define BKT 16
#define SPAD 132

__global__ __launch_bounds__(256) void sgemm_abt(
    const float* __restrict__ A, const float* __restrict__ Bmat,
    float* __restrict__ C, int K, int N,
    long strideB, long strideC)
{
    __shared__ float As[BKT][SPAD];
    __shared__ float Bs[BKT][SPAD];

    const float* Bp = Bmat + (long)blockIdx.z * strideB;
    float* Cp = C + (long)blockIdx.z * strideC;

    const int tid = threadIdx.x;
    const int m0 = blockIdx.y * BMT;
    const int n0 = blockIdx.x * BNT;
    const int tx = tid & 15;      // 0..15 -> 8 cols each
    const int ty = tid >> 4;      // 0..15 -> 8 rows each

    float acc[8][8];
#pragma unroll
    for (int i = 0; i < 8; i++)
#pragma unroll
        for (int j = 0; j < 8; j++) acc[i][j] = 0.f;

    for (int k0 = 0; k0 < K; k0 += BKT) {
#pragma unroll
        for (int i = 0; i < 2; i++) {
            int lin = tid + i * 256;          // 0..511
            int row = lin >> 2;               // 0..127
            int kq  = (lin & 3) << 2;         // 0,4,8,12
            const float4 va = *(const float4*)(A  + (long)(m0 + row) * K + k0 + kq);
            As[kq + 0][row] = va.x; As[kq + 1][row] = va.y;
            As[kq + 2][row] = va.z; As[kq + 3][row] = va.w;
            const float4 vb = *(const float4*)(Bp + (long)(n0 + row) * K + k0 + kq);
            Bs[kq + 0][row] = vb.x; Bs[kq + 1][row] = vb.y;
            Bs[kq + 2][row] = vb.z; Bs[kq + 3][row] = vb.w;
        }
        __syncthreads();

#pragma unroll
        for (int kk = 0; kk < BKT; kk++) {
            float a[8], b[8];
            *(float4*)&a[0] = *(const float4*)&As[kk][ty * 8];
            *(float4*)&a[4] = *(const float4*)&As[kk][ty * 8 + 4];
            *(float4*)&b[0] = *(const float4*)&Bs[kk][tx * 8];
            *(float4*)&b[4] = *(const float4*)&Bs[kk][tx * 8 + 4];
#pragma unroll
            for (int i = 0; i < 8; i++)
#pragma unroll
                for (int j = 0; j < 8; j++)
                    acc[i][j] = fmaf(a[i], b[j], acc[i][j]);
        }
        __syncthreads();
    }

#pragma unroll
    for (int i = 0; i < 8; i++) {
        float* cr = Cp + (long)(m0 + ty * 8 + i) * N + n0 + tx * 8;
        *(float4*)(cr)     = make_float4(acc[i][0], acc[i][1], acc[i][2], acc[i][3]);
        *(float4*)(cr + 4) = make_float4(acc[i][4], acc[i][5], acc[i][6], acc[i][7]);
    }
}

// ---------------- RoPE (in-place, rotate_half) -------------------------------
// X layout: [NLAY*B][L][E] with E index = h*64 + d. Each thread handles pair (d, d+32).
__global__ void rope_kernel(float* __restrict__ X,
                            const float* __restrict__ cosb,
                            const float* __restrict__ sinb)
{
    int idx = blockIdx.x * blockDim.x + threadIdx.x;
    const int total = NLAY * BB * LS * HH * 32;
    if (idx >= total) return;
    int d   = idx & 31;
    int h   = (idx >> 5) & 15;
    int lbl = idx >> 9;                 // (layer*B+b)*L + l
    int l   = lbl & (LS - 1);
    long off = (long)lbl * ES + h * DH + d;
    float x1 = X[off];
    float x2 = X[off + 32];
    float c1 = cosb[l * DH + d],      s1 = sinb[l * DH + d];
    float c2 = cosb[l * DH + d + 32], s2 = sinb[l * DH + d + 32];
    X[off]      = x1 * c1 - x2 * s1;
    X[off + 32] = x2 * c2 + x1 * s2;
}

// ---------------- Flash-style causal attention (fp32) ------------------------
// Grid: (L/64, H, NLAY*B). Block: 128 threads. smem: QsT[64][64] + KsT[64][64]
// + Vs[64][64] + Ps[64][65]. Thread (ty,tx): ty=tid/8 owns query rows ty*4..+3,
// tx=tid%8 owns key/d cols tx*8..+7.
__global__ __launch_bounds__(128) void flash_attn(
    const float* __restrict__ Q, const float* __restrict__ K,
    const float* __restrict__ V, float* __restrict__ O)
{
    extern __shared__ float sm[];
    float* QsT = sm;             // [d][row]
    float* KsT = sm + 4096;      // [d][col]
    float* Vs  = sm + 8192;      // [j][d]
    float* Ps  = sm + 12288;     // [row][65]

    const int qt = blockIdx.x;
    const int h  = blockIdx.y;
    const long base = (long)blockIdx.z * (LS * (long)ES);

    const int tid = threadIdx.x;
    const int tx = tid & 7;
    const int ty = tid >> 3;

    // Load Q tile (transposed to d-major) with attention scale folded in
    for (int i = tid; i < 1024; i += 128) {
        int row = i >> 4;
        int d   = (i & 15) << 2;
        float4 v = *(const float4*)(Q + base + (long)(qt * 64 + row) * ES + h * DH + d);
        QsT[(d + 0) * 64 + row] = v.x * ATT_SCALE;
        QsT[(d + 1) * 64 + row] = v.y * ATT_SCALE;
        QsT[(d + 2) * 64 + row] = v.z * ATT_SCALE;
        QsT[(d + 3) * 64 + row] = v.w * ATT_SCALE;
    }

    float m_i[4], l_i[4], acc[4][8];
#pragma unroll
    for (int r = 0; r < 4; r++) {
        m_i[r] = -1e30f; l_i[r] = 0.f;
#pragma unroll
        for (int c = 0; c < 8; c++) acc[r][c] = 0.f;
    }

    for (int kt = 0; kt <= qt; kt++) {
        __syncthreads();   // protect Q (first iter) & prev-iter KsT/Vs/Ps reads
        for (int i = tid; i < 1024; i += 128) {
            int row = i >> 4;
            int d   = (i & 15) << 2;
            long goff = base + (long)(kt * 64 + row) * ES + h * DH + d;
            float4 kv = *(const float4*)(K + goff);
            KsT[(d + 0) * 64 + row] = kv.x;
            KsT[(d + 1) * 64 + row] = kv.y;
            KsT[(d + 2) * 64 + row] = kv.z;
            KsT[(d + 3) * 64 + row] = kv.w;
            *(float4*)(Vs + row * 64 + d) = *(const float4*)(V + goff);
        }
        __syncthreads();

        // S = Q K^T  (64x64 tile)
        float s[4][8];
#pragma unroll
        for (int r = 0; r < 4; r++)
#pragma unroll
            for (int c = 0; c < 8; c++) s[r][c] = 0.f;

#pragma unroll 4
        for (int d = 0; d < 64; d++) {
            float a[4], b[8];
            *(float4*)&a[0] = *(const float4*)&QsT[d * 64 + ty * 4];
            *(float4*)&b[0] = *(const float4*)&KsT[d * 64 + tx * 8];
            *(float4*)&b[4] = *(const float4*)&KsT[d * 64 + tx * 8 + 4];
#pragma unroll
            for (int r = 0; r < 4; r++)
#pragma unroll
                for (int c = 0; c < 8; c++)
                    s[r][c] = fmaf(a[r], b[c], s[r][c]);
        }

        if (kt == qt) {  // diagonal tile: causal mask (same tile -> local compare)
#pragma unroll
            for (int r = 0; r < 4; r++)
#pragma unroll
                for (int c = 0; c < 8; c++)
                    if (tx * 8 + c > ty * 4 + r) s[r][c] = -1e30f;
        }

        // online softmax update
#pragma unroll
        for (int r = 0; r < 4; r++) {
            float mx = s[r][0];
#pragma unroll
            for (int c = 1; c < 8; c++) mx = fmaxf(mx, s[r][c]);
            mx = fmaxf(mx, __shfl_xor_sync(0xffffffffu, mx, 1));
            mx = fmaxf(mx, __shfl_xor_sync(0xffffffffu, mx, 2));
            mx = fmaxf(mx, __shfl_xor_sync(0xffffffffu, mx, 4));
            float mnew = fmaxf(m_i[r], mx);
            float f = __expf(m_i[r] - mnew);
            m_i[r] = mnew;
            float rs = 0.f;
#pragma unroll
            for (int c = 0; c < 8; c++) {
                float p = __expf(s[r][c] - mnew);
                s[r][c] = p;
                rs += p;
            }
            rs += __shfl_xor_sync(0xffffffffu, rs, 1);
            rs += __shfl_xor_sync(0xffffffffu, rs, 2);
            rs += __shfl_xor_sync(0xffffffffu, rs, 4);
            l_i[r] = l_i[r] * f + rs;
#pragma unroll
            for (int c = 0; c < 8; c++) acc[r][c] *= f;
#pragma unroll
            for (int c = 0; c < 8; c++)
                Ps[(ty * 4 + r) * 65 + tx * 8 + c] = s[r][c];
        }
        __syncthreads();

        // O += P @ V
#pragma unroll 4
        for (int j = 0; j < 64; j++) {
            float bv[8];
            *(float4*)&bv[0] = *(const float4*)&Vs[j * 64 + tx * 8];
            *(float4*)&bv[4] = *(const float4*)&Vs[j * 64 + tx * 8 + 4];
#pragma unroll
            for (int r = 0; r < 4; r++) {
                float p = Ps[(ty * 4 + r) * 65 + j];
#pragma unroll
                for (int c = 0; c < 8; c++)
                    acc[r][c] = fmaf(p, bv[c], acc[r][c]);
            }
        }
    }

    // epilogue
#pragma unroll
    for (int r = 0; r < 4; r++) {
        float inv = 1.f / l_i[r];
        long o = base + (long)(qt * 64 + ty * 4 + r) * ES + h * DH + tx * 8;
        O[o + 0] = acc[r][0] * inv; O[o + 1] = acc[r][1] * inv;
        O[o + 2] = acc[r][2] * inv; O[o + 3] = acc[r][3] * inv;
        O[o + 4] = acc[r][4] * inv; O[o + 5] = acc[r][5] * inv;
        O[o + 6] = acc[r][6] * inv; O[o + 7] = acc[r][7] * inv;
    }
}

// ---------------- per-row combine: rmsnorm x3, lambda mix, residual, final RMS
__device__ __forceinline__ float blockSum256(float v)
{
    __shared__ float sh[8];
    __shared__ float total;
    int lane = threadIdx.x & 31, warp = threadIdx.x >> 5;
#pragma unroll
    for (int o = 16; o; o >>= 1) v += __shfl_xor_sync(0xffffffffu, v, o);
    __syncthreads();                 // protect sh across successive calls
    if (lane == 0) sh[warp] = v;
    __syncthreads();
    if (threadIdx.x == 0) {
        float t = 0.f;
#pragma unroll
        for (int i = 0; i < 8; i++) t += sh[i];
        total = t;
    }
    __syncthreads();
    return total;
}

__global__ __launch_bounds__(256) void combine_kernel(
    const float* __restrict__ A,        // [NLAY][B*L][E]
    const float* __restrict__ x,        // [B*L][E]
    const float* __restrict__ g_ln,     // [NLAY][E]
    const float* __restrict__ lambdas,  // [NLAY]
    const float* __restrict__ g_final,  // [E]
    const float* __restrict__ alpha,    // [1]
    float* __restrict__ Y)              // [B*L][E]
{
    const int row = blockIdx.x;
    const int tid = threadIdx.x;
    const int e0  = tid * 4;

    // lambda weights: sigmoid -> non-affine LN over the 3 values
    float sg0 = 1.f / (1.f + __expf(-lambdas[0]));
    float sg1 = 1.f / (1.f + __expf(-lambdas[1]));
    float sg2 = 1.f / (1.f + __expf(-lambdas[2]));
    float mu  = (sg0 + sg1 + sg2) * (1.f / 3.f);
    float va  = ((sg0 - mu) * (sg0 - mu) + (sg1 - mu) * (sg1 - mu) +
                 (sg2 - mu) * (sg2 - mu)) * (1.f / 3.f);
    float ivs = rsqrtf(va + EPSF);
    float lw0 = (sg0 - mu) * ivs, lw1 = (sg1 - mu) * ivs, lw2 = (sg2 - mu) * ivs;

    long ro = (long)row * ES + e0;
    float4 a0 = *(const float4*)(A + 0L * LAYER_ELEMS + ro);
    float4 a1 = *(const float4*)(A + 1L * LAYER_ELEMS + ro);
    float4 a2 = *(const float4*)(A + 2L * LAYER_ELEMS + ro);
    float4 xv = *(const float4*)(x + ro);

    float ss0 = blockSum256(a0.x*a0.x + a0.y*a0.y + a0.z*a0.z + a0.w*a0.w);
    float ss1 = blockSum256(a1.x*a1.x + a1.y*a1.y + a1.z*a1.z + a1.w*a1.w);
    float ss2 = blockSum256(a2.x*a2.x + a2.y*a2.y + a2.z*a2.z + a2.w*a2.w);

    float r0 = rsqrtf(ss0 * (1.f / ES) + EPSF) * lw0;
    float r1 = rsqrtf(ss1 * (1.f / ES) + EPSF) * lw1;
    float r2 = rsqrtf(ss2 * (1.f / ES) + EPSF) * lw2;
    float al = alpha[0];

    float4 g0 = *(const float4*)(g_ln + 0 * ES + e0);
    float4 g1 = *(const float4*)(g_ln + 1 * ES + e0);
    float4 g2 = *(const float4*)(g_ln + 2 * ES + e0);

    float4 cb;
    cb.x = a0.x*r0*g0.x + a1.x*r1*g1.x + a2.x*r2*g2.x + al*xv.x;
    cb.y = a0.y*r0*g0.y + a1.y*r1*g1.y + a2.y*r2*g2.y + al*xv.y;
    cb.z = a0.z*r0*g0.z + a1.z*r1*g1.z + a2.z*r2*g2.z + al*xv.z;
    cb.w = a0.w*r0*g0.w + a1.w*r1*g1.w + a2.w*r2*g2.w + al*xv.w;

    float ssc = blockSum256(cb.x*cb.x + cb.y*cb.y + cb.z*cb.z + cb.w*cb.w);
    float rc  = rsqrtf(ssc * (1.f / ES) + EPSF);

    float4 gf = *(const float4*)(g_final + e0);
    float4 yv;
    yv.x = cb.x * rc * gf.x; yv.y = cb.y * rc * gf.y;
    yv.z = cb.z * rc * gf.z; yv.w = cb.w * rc * gf.w;
    *(float4*)(Y + ro) = yv;
}

// ---------------- launch ------------------------------------------------------
extern "C" void kernel_launch(void* const* d_in, const int* in_sizes, int n_in,
                              void* d_out, int out_size)
{
    const float* x       = (const float*)d_in[0];
    const float* cosb    = (const float*)d_in[1];
    const float* sinb    = (const float*)d_in[2];
    // d_in[3] = attn_mask (pure causal; implemented directly)
    const float* Wq      = (const float*)d_in[4];
    const float* Wk      = (const float*)d_in[5];
    const float* Wv      = (const float*)d_in[6];
    const float* g_ln    = (const float*)d_in[7];
    const float* lambdas = (const float*)d_in[8];
    const float* Wo      = (const float*)d_in[9];
    const float* g_final = (const float*)d_in[10];
    const float* alpha   = (const float*)d_in[11];
    float* out = (float*)d_out;

    float *qb, *kb, *vb, *ab, *yb;
    cudaGetSymbolAddress((void**)&qb, d_QB);
    cudaGetSymbolAddress((void**)&kb, d_KB);
    cudaGetSymbolAddress((void**)&vb, d_VB);
    cudaGetSymbolAddress((void**)&ab, d_AB);
    cudaGetSymbolAddress((void**)&yb, d_YB);

    // 1) projections: 9 GEMMs (3 launches, grid.z = layer)
    dim3 gproj(ES / BNT, MROWS / BMT, NLAY);
    sgemm_abt<<<gproj, 256>>>(x, Wq, qb, ES, ES, (long)ES * ES, (long)LAYER_ELEMS);
    sgemm_abt<<<gproj, 256>>>(x, Wk, kb, ES, ES, (long)ES * ES, (long)LAYER_ELEMS);
    sgemm_abt<<<gproj, 256>>>(x, Wv, vb, ES, ES, (long)ES * ES, (long)LAYER_ELEMS);

    // 2) rope on Q and K (in place)
    const int rope_total = NLAY * BB * LS * HH * 32;
    rope_kernel<<<rope_total / 256, 256>>>(qb, cosb, sinb);
    rope_kernel<<<rope_total / 256, 256>>>(kb, cosb, sinb);

    // 3) flash attention over all (layer, batch, head, qtile)
    const int smem_bytes = (3 * 64 * 64 + 64 * 65) * 4;   // 65792
    cudaFuncSetAttribute(flash_attn, cudaFuncAttributeMaxDynamicSharedMemorySize,
                         smem_bytes);
    flash_attn<<<dim3(LS / 64, HH, NLAY * BB), 128, smem_bytes>>>(qb, kb, vb, ab);

    // 4) per-row norms + lambda combine + residual + final rmsnorm
    combine_kernel<<<MROWS, 256>>>(ab, x, g_ln, lambdas, g_final, alpha, yb);

    // 5) output projection
    sgemm_abt<<<dim3(ES / BNT, MROWS / BMT, 1), 256>>>(yb, Wo, out, ES, ES, 0, 0);
}

// round 6
// speedup vs baseline: 1.5205x; 1.5205x over previous
#include <cuda_runtime.h>
#include <cuda_bf16.h>
#include <cstdint>

// Problem constants
#define NLAY 3
#define BB   2
#define LS   1024
#define ES   1024
#define HH   16
#define DH   64
#define MROWS (BB*LS)              // 2048
#define LAYER_ELEMS (BB*LS*ES)     // 2097152
#define ATT_SCALE 0.125f           // D^-0.5 = 1/8
#define EPSF 1e-5f

// ---------------- scratch (static device allocations; no cudaMalloc) --------
__device__ float d_QB[NLAY * LAYER_ELEMS];
__device__ float d_KB[NLAY * LAYER_ELEMS];
__device__ float d_VB[NLAY * LAYER_ELEMS];
__device__ float d_AB[NLAY * LAYER_ELEMS];
__device__ float d_YB[LAYER_ELEMS];

// =============================================================================
// TF32 tensor-core GEMM: C = A @ B^T
// A: M x K row-major, Bmat: N x K row-major, C: M x N row-major.
// Blocktile 128x128x32, 256 threads = 8 warps (4 M x 2 N), warptile 32x64.
// mma.sync.aligned.m16n8k8.row.col.f32.tf32.tf32.f32
// Smem [row][k] stride 36 -> fragment LDS addresses (4*gr+gc) mod 32 cover all
// banks: conflict-free. Double-buffered; inputs rounded to tf32 with cvt.rna.
// =============================================================================
#define TBM 128
#define TBN 128
#define TBK 32
#define TLDS 36
#define TILE_F (TBM * TLDS)          // floats per tile (4608)
#define BUF_F  (2 * TILE_F)          // A+B per buffer (9216)

__device__ __forceinline__ uint32_t f2tf32(float x) {
    uint32_t u;
    asm("cvt.rna.tf32.f32 %0, %1;" : "=r"(u) : "f"(x));
    return u;
}

__device__ __forceinline__ void mma_tf32(
    float c[4], const uint32_t a[4], const uint32_t b[2])
{
    asm volatile(
        "mma.sync.aligned.m16n8k8.row.col.f32.tf32.tf32.f32 "
        "{%0,%1,%2,%3}, {%4,%5,%6,%7}, {%8,%9}, {%0,%1,%2,%3};"
        : "+f"(c[0]), "+f"(c[1]), "+f"(c[2]), "+f"(c[3])
        : "r"(a[0]), "r"(a[1]), "r"(a[2]), "r"(a[3]),
          "r"(b[0]), "r"(b[1]));
}

__global__ __launch_bounds__(256) void tf32_gemm_abt(
    const float* __restrict__ A, const float* __restrict__ Bmat,
    float* __restrict__ C, int K, int N,
    long strideB, long strideC)
{
    extern __shared__ uint32_t smu[];

    const float* Bp = Bmat + (long)blockIdx.z * strideB;
    float* Cp = C + (long)blockIdx.z * strideC;

    const int tid  = threadIdx.x;
    const int m0   = blockIdx.y * TBM;
    const int n0   = blockIdx.x * TBN;
    const int warp = tid >> 5, lane = tid & 31;
    const int wm = warp & 3;          // 0..3 -> 32 M rows each
    const int wn = warp >> 2;         // 0..1 -> 64 N cols each
    const int gr = lane >> 2;         // 0..7
    const int gc = lane & 3;          // 0..3

    // copy indexing: 1024 float4 per 128x32 tile, 4 per thread
    const int crow = tid >> 3;        // base row 0..31 (stride 32 over i)
    const int ccol = (tid & 7) << 2;  // 0,4,...,28

    float acc[2][8][4];
#pragma unroll
    for (int mt = 0; mt < 2; mt++)
#pragma unroll
        for (int nt = 0; nt < 8; nt++)
#pragma unroll
            for (int c = 0; c < 4; c++) acc[mt][nt][c] = 0.f;

    uint32_t stA[4][4], stB[4][4];
    const int KT = K / TBK;

    // ---- prologue: load tile 0 -> regs -> smem buf0 ----
#pragma unroll
    for (int i = 0; i < 4; i++) {
        int r = crow + i * 32;
        float4 va = *(const float4*)(A  + (long)(m0 + r) * K + ccol);
        float4 vb = *(const float4*)(Bp + (long)(n0 + r) * K + ccol);
        stA[i][0] = f2tf32(va.x); stA[i][1] = f2tf32(va.y);
        stA[i][2] = f2tf32(va.z); stA[i][3] = f2tf32(va.w);
        stB[i][0] = f2tf32(vb.x); stB[i][1] = f2tf32(vb.y);
        stB[i][2] = f2tf32(vb.z); stB[i][3] = f2tf32(vb.w);
    }
#pragma unroll
    for (int i = 0; i < 4; i++) {
        int r = crow + i * 32;
        uint32_t* as = smu + r * TLDS + ccol;
        uint32_t* bs = smu + TILE_F + r * TLDS + ccol;
#pragma unroll
        for (int j = 0; j < 4; j++) { as[j] = stA[i][j]; bs[j] = stB[i][j]; }
    }
    __syncthreads();

    for (int kt = 0; kt < KT; kt++) {
        const int cur = kt & 1;
        const uint32_t* As = smu + cur * BUF_F;
        const uint32_t* Bs = As + TILE_F;

        // prefetch next tile into regs
        if (kt + 1 < KT) {
            int k0 = (kt + 1) * TBK;
#pragma unroll
            for (int i = 0; i < 4; i++) {
                int r = crow + i * 32;
                float4 va = *(const float4*)(A  + (long)(m0 + r) * K + k0 + ccol);
                float4 vb = *(const float4*)(Bp + (long)(n0 + r) * K + k0 + ccol);
                stA[i][0] = f2tf32(va.x); stA[i][1] = f2tf32(va.y);
                stA[i][2] = f2tf32(va.z); stA[i][3] = f2tf32(va.w);
                stB[i][0] = f2tf32(vb.x); stB[i][1] = f2tf32(vb.y);
                stB[i][2] = f2tf32(vb.z); stB[i][3] = f2tf32(vb.w);
            }
        }

        // compute over 4 k=8 sub-steps
#pragma unroll
        for (int kk = 0; kk < TBK; kk += 8) {
            uint32_t af[2][4], bf[8][2];
#pragma unroll
            for (int mt = 0; mt < 2; mt++) {
                int r = wm * 32 + mt * 16 + gr;
                af[mt][0] = As[(r    ) * TLDS + kk + gc];
                af[mt][1] = As[(r + 8) * TLDS + kk + gc];
                af[mt][2] = As[(r    ) * TLDS + kk + gc + 4];
                af[mt][3] = As[(r + 8) * TLDS + kk + gc + 4];
            }
#pragma unroll
            for (int nt = 0; nt < 8; nt++) {
                int cidx = wn * 64 + nt * 8 + gr;
                bf[nt][0] = Bs[cidx * TLDS + kk + gc];
                bf[nt][1] = Bs[cidx * TLDS + kk + gc + 4];
            }
#pragma unroll
            for (int mt = 0; mt < 2; mt++)
#pragma unroll
                for (int nt = 0; nt < 8; nt++)
                    mma_tf32(acc[mt][nt], af[mt], bf[nt]);
        }

        if (kt + 1 < KT) {
            __syncthreads();
            uint32_t* nb = smu + ((kt + 1) & 1) * BUF_F;
#pragma unroll
            for (int i = 0; i < 4; i++) {
                int r = crow + i * 32;
                uint32_t* as = nb + r * TLDS + ccol;
                uint32_t* bs = nb + TILE_F + r * TLDS + ccol;
#pragma unroll
                for (int j = 0; j < 4; j++) { as[j] = stA[i][j]; bs[j] = stB[i][j]; }
            }
            __syncthreads();
        }
    }

    // epilogue
#pragma unroll
    for (int mt = 0; mt < 2; mt++) {
        int r0 = m0 + wm * 32 + mt * 16 + gr;
#pragma unroll
        for (int nt = 0; nt < 8; nt++) {
            int cc = n0 + wn * 64 + nt * 8 + gc * 2;
            *(float2*)(Cp + (long)r0 * N + cc) =
                make_float2(acc[mt][nt][0], acc[mt][nt][1]);
            *(float2*)(Cp + (long)(r0 + 8) * N + cc) =
                make_float2(acc[mt][nt][2], acc[mt][nt][3]);
        }
    }
}

// ---------------- RoPE (in-place, rotate_half) -------------------------------
__global__ void rope_kernel(float* __restrict__ X,
                            const float* __restrict__ cosb,
                            const float* __restrict__ sinb)
{
    int idx = blockIdx.x * blockDim.x + threadIdx.x;
    const int total = NLAY * BB * LS * HH * 32;
    if (idx >= total) return;
    int d   = idx & 31;
    int h   = (idx >> 5) & 15;
    int lbl = idx >> 9;                 // (layer*B+b)*L + l
    int l   = lbl & (LS - 1);
    long off = (long)lbl * ES + h * DH + d;
    float x1 = X[off];
    float x2 = X[off + 32];
    float c1 = cosb[l * DH + d],      s1 = sinb[l * DH + d];
    float c2 = cosb[l * DH + d + 32], s2 = sinb[l * DH + d + 32];
    X[off]      = x1 * c1 - x2 * s1;
    X[off + 32] = x2 * c2 + x1 * s2;
}

// ---------------- Flash-style causal attention (fp32) ------------------------
__global__ __launch_bounds__(128) void flash_attn(
    const float* __restrict__ Q, const float* __restrict__ K,
    const float* __restrict__ V, float* __restrict__ O)
{
    extern __shared__ float sm[];
    float* QsT = sm;             // [d][row]
    float* KsT = sm + 4096;      // [d][col]
    float* Vs  = sm + 8192;      // [j][d]
    float* Ps  = sm + 12288;     // [row][65]

    const int qt = blockIdx.x;
    const int h  = blockIdx.y;
    const long base = (long)blockIdx.z * (LS * (long)ES);

    const int tid = threadIdx.x;
    const int tx = tid & 7;
    const int ty = tid >> 3;

    for (int i = tid; i < 1024; i += 128) {
        int row = i >> 4;
        int d   = (i & 15) << 2;
        float4 v = *(const float4*)(Q + base + (long)(qt * 64 + row) * ES + h * DH + d);
        QsT[(d + 0) * 64 + row] = v.x * ATT_SCALE;
        QsT[(d + 1) * 64 + row] = v.y * ATT_SCALE;
        QsT[(d + 2) * 64 + row] = v.z * ATT_SCALE;
        QsT[(d + 3) * 64 + row] = v.w * ATT_SCALE;
    }

    float m_i[4], l_i[4], acc[4][8];
#pragma unroll
    for (int r = 0; r < 4; r++) {
        m_i[r] = -1e30f; l_i[r] = 0.f;
#pragma unroll
        for (int c = 0; c < 8; c++) acc[r][c] = 0.f;
    }

    for (int kt = 0; kt <= qt; kt++) {
        __syncthreads();
        for (int i = tid; i < 1024; i += 128) {
            int row = i >> 4;
            int d   = (i & 15) << 2;
            long goff = base + (long)(kt * 64 + row) * ES + h * DH + d;
            float4 kv = *(const float4*)(K + goff);
            KsT[(d + 0) * 64 + row] = kv.x;
            KsT[(d + 1) * 64 + row] = kv.y;
            KsT[(d + 2) * 64 + row] = kv.z;
            KsT[(d + 3) * 64 + row] = kv.w;
            *(float4*)(Vs + row * 64 + d) = *(const float4*)(V + goff);
        }
        __syncthreads();

        float s[4][8];
#pragma unroll
        for (int r = 0; r < 4; r++)
#pragma unroll
            for (int c = 0; c < 8; c++) s[r][c] = 0.f;

#pragma unroll 4
        for (int d = 0; d < 64; d++) {
            float a[4], b[8];
            *(float4*)&a[0] = *(const float4*)&QsT[d * 64 + ty * 4];
            *(float4*)&b[0] = *(const float4*)&KsT[d * 64 + tx * 8];
            *(float4*)&b[4] = *(const float4*)&KsT[d * 64 + tx * 8 + 4];
#pragma unroll
            for (int r = 0; r < 4; r++)
#pragma unroll
                for (int c = 0; c < 8; c++)
                    s[r][c] = fmaf(a[r], b[c], s[r][c]);
        }

        if (kt == qt) {
#pragma unroll
            for (int r = 0; r < 4; r++)
#pragma unroll
                for (int c = 0; c < 8; c++)
                    if (tx * 8 + c > ty * 4 + r) s[r][c] = -1e30f;
        }

#pragma unroll
        for (int r = 0; r < 4; r++) {
            float mx = s[r][0];
#pragma unroll
            for (int c = 1; c < 8; c++) mx = fmaxf(mx, s[r][c]);
            mx = fmaxf(mx, __shfl_xor_sync(0xffffffffu, mx, 1));
            mx = fmaxf(mx, __shfl_xor_sync(0xffffffffu, mx, 2));
            mx = fmaxf(mx, __shfl_xor_sync(0xffffffffu, mx, 4));
            float mnew = fmaxf(m_i[r], mx);
            float f = __expf(m_i[r] - mnew);
            m_i[r] = mnew;
            float rs = 0.f;
#pragma unroll
            for (int c = 0; c < 8; c++) {
                float p = __expf(s[r][c] - mnew);
                s[r][c] = p;
                rs += p;
            }
            rs += __shfl_xor_sync(0xffffffffu, rs, 1);
            rs += __shfl_xor_sync(0xffffffffu, rs, 2);
            rs += __shfl_xor_sync(0xffffffffu, rs, 4);
            l_i[r] = l_i[r] * f + rs;
#pragma unroll
            for (int c = 0; c < 8; c++) acc[r][c] *= f;
#pragma unroll
            for (int c = 0; c < 8; c++)
                Ps[(ty * 4 + r) * 65 + tx * 8 + c] = s[r][c];
        }
        __syncthreads();

#pragma unroll 4
        for (int j = 0; j < 64; j++) {
            float bv[8];
            *(float4*)&bv[0] = *(const float4*)&Vs[j * 64 + tx * 8];
            *(float4*)&bv[4] = *(const float4*)&Vs[j * 64 + tx * 8 + 4];
#pragma unroll
            for (int r = 0; r < 4; r++) {
                float p = Ps[(ty * 4 + r) * 65 + j];
#pragma unroll
                for (int c = 0; c < 8; c++)
                    acc[r][c] = fmaf(p, bv[c], acc[r][c]);
            }
        }
    }

#pragma unroll
    for (int r = 0; r < 4; r++) {
        float inv = 1.f / l_i[r];
        long o = base + (long)(qt * 64 + ty * 4 + r) * ES + h * DH + tx * 8;
        O[o + 0] = acc[r][0] * inv; O[o + 1] = acc[r][1] * inv;
        O[o + 2] = acc[r][2] * inv; O[o + 3] = acc[r][3] * inv;
        O[o + 4] = acc[r][4] * inv; O[o + 5] = acc[r][5] * inv;
        O[o + 6] = acc[r][6] * inv; O[o + 7] = acc[r][7] * inv;
    }
}

// ---------------- per-row combine -------------------------------------------
__device__ __forceinline__ float blockSum256(float v)
{
    __shared__ float sh[8];
    __shared__ float total;
    int lane = threadIdx.x & 31, warp = threadIdx.x >> 5;
#pragma unroll
    for (int o = 16; o; o >>= 1) v += __shfl_xor_sync(0xffffffffu, v, o);
    __syncthreads();
    if (lane == 0) sh[warp] = v;
    __syncthreads();
    if (threadIdx.x == 0) {
        float t = 0.f;
#pragma unroll
        for (int i = 0; i < 8; i++) t += sh[i];
        total = t;
    }
    __syncthreads();
    return total;
}

__global__ __launch_bounds__(256) void combine_kernel(
    const float* __restrict__ A,
    const float* __restrict__ x,
    const float* __restrict__ g_ln,
    const float* __restrict__ lambdas,
    const float* __restrict__ g_final,
    const float* __restrict__ alpha,
    float* __restrict__ Y)
{
    const int row = blockIdx.x;
    const int tid = threadIdx.x;
    const int e0  = tid * 4;

    float sg0 = 1.f / (1.f + __expf(-lambdas[0]));
    float sg1 = 1.f / (1.f + __expf(-lambdas[1]));
    float sg2 = 1.f / (1.f + __expf(-lambdas[2]));
    float mu  = (sg0 + sg1 + sg2) * (1.f / 3.f);
    float va  = ((sg0 - mu) * (sg0 - mu) + (sg1 - mu) * (sg1 - mu) +
                 (sg2 - mu) * (sg2 - mu)) * (1.f / 3.f);
    float ivs = rsqrtf(va + EPSF);
    float lw0 = (sg0 - mu) * ivs, lw1 = (sg1 - mu) * ivs, lw2 = (sg2 - mu) * ivs;

    long ro = (long)row * ES + e0;
    float4 a0 = *(const float4*)(A + 0L * LAYER_ELEMS + ro);
    float4 a1 = *(const float4*)(A + 1L * LAYER_ELEMS + ro);
    float4 a2 = *(const float4*)(A + 2L * LAYER_ELEMS + ro);
    float4 xv = *(const float4*)(x + ro);

    float ss0 = blockSum256(a0.x*a0.x + a0.y*a0.y + a0.z*a0.z + a0.w*a0.w);
    float ss1 = blockSum256(a1.x*a1.x + a1.y*a1.y + a1.z*a1.z + a1.w*a1.w);
    float ss2 = blockSum256(a2.x*a2.x + a2.y*a2.y + a2.z*a2.z + a2.w*a2.w);

    float r0 = rsqrtf(ss0 * (1.f / ES) + EPSF) * lw0;
    float r1 = rsqrtf(ss1 * (1.f / ES) + EPSF) * lw1;
    float r2 = rsqrtf(ss2 * (1.f / ES) + EPSF) * lw2;
    float al = alpha[0];

    float4 g0 = *(const float4*)(g_ln + 0 * ES + e0);
    float4 g1 = *(const float4*)(g_ln + 1 * ES + e0);
    float4 g2 = *(const float4*)(g_ln + 2 * ES + e0);

    float4 cb;
    cb.x = a0.x*r0*g0.x + a1.x*r1*g1.x + a2.x*r2*g2.x + al*xv.x;
    cb.y = a0.y*r0*g0.y + a1.y*r1*g1.y + a2.y*r2*g2.y + al*xv.y;
    cb.z = a0.z*r0*g0.z + a1.z*r1*g1.z + a2.z*r2*g2.z + al*xv.z;
    cb.w = a0.w*r0*g0.w + a1.w*r1*g1.w + a2.w*r2*g2.w + al*xv.w;

    float ssc = blockSum256(cb.x*cb.x + cb.y*cb.y + cb.z*cb.z + cb.w*cb.w);
    float rc  = rsqrtf(ssc * (1.f / ES) + EPSF);

    float4 gf = *(const float4*)(g_final + e0);
    float4 yv;
    yv.x = cb.x * rc * gf.x; yv.y = cb.y * rc * gf.y;
    yv.z = cb.z * rc * gf.z; yv.w = cb.w * rc * gf.w;
    *(float4*)(Y + ro) = yv;
}

// ---------------- launch ------------------------------------------------------
extern "C" void kernel_launch(void* const* d_in, const int* in_sizes, int n_in,
                              void* d_out, int out_size)
{
    const float* x       = (const float*)d_in[0];
    const float* cosb    = (const float*)d_in[1];
    const float* sinb    = (const float*)d_in[2];
    // d_in[3] = attn_mask (pure causal; implemented directly)
    const float* Wq      = (const float*)d_in[4];
    const float* Wk      = (const float*)d_in[5];
    const float* Wv      = (const float*)d_in[6];
    const float* g_ln    = (const float*)d_in[7];
    const float* lambdas = (const float*)d_in[8];
    const float* Wo      = (const float*)d_in[9];
    const float* g_final = (const float*)d_in[10];
    const float* alpha   = (const float*)d_in[11];
    float* out = (float*)d_out;

    float *qb, *kb, *vb, *ab, *yb;
    cudaGetSymbolAddress((void**)&qb, d_QB);
    cudaGetSymbolAddress((void**)&kb, d_KB);
    cudaGetSymbolAddress((void**)&vb, d_VB);
    cudaGetSymbolAddress((void**)&ab, d_AB);
    cudaGetSymbolAddress((void**)&yb, d_YB);

    const int gemm_smem = 2 * BUF_F * 4;   // 73728 bytes
    static int smem_set = 0;
    if (!smem_set) {
        cudaFuncSetAttribute(tf32_gemm_abt,
                             cudaFuncAttributeMaxDynamicSharedMemorySize, gemm_smem);
        smem_set = 1;
    }

    // 1) projections: 9 GEMMs (3 launches, grid.z = layer)
    dim3 gproj(ES / TBN, MROWS / TBM, NLAY);
    tf32_gemm_abt<<<gproj, 256, gemm_smem>>>(x, Wq, qb, ES, ES,
                                             (long)ES * ES, (long)LAYER_ELEMS);
    tf32_gemm_abt<<<gproj, 256, gemm_smem>>>(x, Wk, kb, ES, ES,
                                             (long)ES * ES, (long)LAYER_ELEMS);
    tf32_gemm_abt<<<gproj, 256, gemm_smem>>>(x, Wv, vb, ES, ES,
                                             (long)ES * ES, (long)LAYER_ELEMS);

    // 2) rope on Q and K (in place)
    const int rope_total = NLAY * BB * LS * HH * 32;
    rope_kernel<<<rope_total / 256, 256>>>(qb, cosb, sinb);
    rope_kernel<<<rope_total / 256, 256>>>(kb, cosb, sinb);

    // 3) flash attention over all (layer, batch, head, qtile)
    const int smem_bytes = (3 * 64 * 64 + 64 * 65) * 4;   // 65792
    cudaFuncSetAttribute(flash_attn, cudaFuncAttributeMaxDynamicSharedMemorySize,
                         smem_bytes);
    flash_attn<<<dim3(LS / 64, HH, NLAY * BB), 128, smem_bytes>>>(qb, kb, vb, ab);

    // 4) per-row norms + lambda combine + residual + final rmsnorm
    combine_kernel<<<MROWS, 256>>>(ab, x, g_ln, lambdas, g_final, alpha, yb);

    // 5) output projection
    tf32_gemm_abt<<<dim3(ES / TBN, MROWS / TBM, 1), 256, gemm_smem>>>(
        yb, Wo, out, ES, ES, 0, 0);
}

// round 11
// speedup vs baseline: 1.8267x; 1.2014x over previous
#include <cuda_runtime.h>
#include <cuda_bf16.h>
#include <cstdint>

// Problem constants
#define NLAY 3
#define BB   2
#define LS   1024
#define ES   1024
#define HH   16
#define DH   64
#define MROWS (BB*LS)              // 2048
#define LAYER_ELEMS (BB*LS*ES)     // 2097152
#define ATT_SCALE 0.125f           // D^-0.5 = 1/8
#define EPSF 1e-5f

// ---------------- scratch (static device allocations; no cudaMalloc) --------
__device__ float d_QB[NLAY * LAYER_ELEMS];
__device__ float d_KB[NLAY * LAYER_ELEMS];
__device__ float d_VB[NLAY * LAYER_ELEMS];
__device__ float d_AB[NLAY * LAYER_ELEMS];
__device__ float d_YB[LAYER_ELEMS];

// =============================================================================
// TF32 tensor-core GEMM: C = A @ W^T  (M x 1024) @ (1024 x 1024)
// Blocktile 128x128x32, 256 thr = 8 warps (4M x 2N), warptile 32x64.
// cp.async 2-stage global->smem (raw fp32), ldmatrix.x4 fragment loads,
// cvt.rna.tf32 applied on fragments. Optional fused RoPE epilogue.
// =============================================================================
#define TBM 128
#define TBN 128
#define TBK 32
#define TLDS 36
#define TILE_F (TBM * TLDS)          // 4608 floats
#define BUF_F  (2 * TILE_F)          // 9216 floats (A+B)
#define GEMM_SMEM (2 * BUF_F * 4)    // 73728 bytes

__device__ __forceinline__ uint32_t f2tf32_u(uint32_t bits) {
    uint32_t u;
    asm("cvt.rna.tf32.f32 %0, %1;" : "=r"(u) : "f"(__uint_as_float(bits)));
    return u;
}

__device__ __forceinline__ void mma_tf32(
    float c[4], const uint32_t a[4], const uint32_t b[2])
{
    asm volatile(
        "mma.sync.aligned.m16n8k8.row.col.f32.tf32.tf32.f32 "
        "{%0,%1,%2,%3}, {%4,%5,%6,%7}, {%8,%9}, {%0,%1,%2,%3};"
        : "+f"(c[0]), "+f"(c[1]), "+f"(c[2]), "+f"(c[3])
        : "r"(a[0]), "r"(a[1]), "r"(a[2]), "r"(a[3]),
          "r"(b[0]), "r"(b[1]));
}

__device__ __forceinline__ void cp16(uint32_t dst, const void* src) {
    asm volatile("cp.async.cg.shared.global [%0], [%1], 16;" :: "r"(dst), "l"(src));
}
__device__ __forceinline__ void cp_commit() {
    asm volatile("cp.async.commit_group;");
}
__device__ __forceinline__ void cp_wait0() {
    asm volatile("cp.async.wait_group 0;");
}

#define LDSM4(r0, r1, r2, r3, addr) \
    asm volatile("ldmatrix.sync.aligned.m8n8.x4.shared.b16 {%0,%1,%2,%3}, [%4];" \
                 : "=r"(r0), "=r"(r1), "=r"(r2), "=r"(r3) : "r"(addr))

__device__ __forceinline__ void gemm_core(
    const float* __restrict__ A, const float* __restrict__ W,
    float* __restrict__ Cp,
    const float* __restrict__ cosb, const float* __restrict__ sinb,
    int do_rope, char* smem)
{
    const int tid  = threadIdx.x;
    const int m0   = blockIdx.y * TBM;
    const int n0   = blockIdx.x * TBN;
    const int warp = tid >> 5, lane = tid & 31;
    const int wm = warp & 3;          // 0..3 -> 32 M rows each
    const int wn = warp >> 2;         // 0..1 -> 64 N cols each
    const int gr = lane >> 2;         // 0..7
    const int gc = lane & 3;          // 0..3

    const uint32_t sbase = (uint32_t)__cvta_generic_to_shared(smem);

    // ldmatrix per-thread source rows/offsets
    const int a_row_in = (lane & 7) + ((lane >> 3) & 1) * 8;   // 0..15
    const int a_koff   = (lane >> 4) * 4;                       // 0 or 4
    const int b_n_in   = (lane & 7) + (lane >> 4) * 8;          // 0..15
    const int b_koff   = ((lane >> 3) & 1) * 4;                 // 0 or 4

    // cp.async indexing: 32 rows x 32 k-floats per (thread, i)
    const int crow = tid >> 3;        // 0..31
    const int ccol = (tid & 7) << 2;  // 0,4,...,28

    float acc[2][8][4];
#pragma unroll
    for (int mt = 0; mt < 2; mt++)
#pragma unroll
        for (int nt = 0; nt < 8; nt++)
#pragma unroll
            for (int c = 0; c < 4; c++) acc[mt][nt][c] = 0.f;

    const int KT = ES / TBK;          // 32

    // prologue: tile 0 in flight
    {
#pragma unroll
        for (int i = 0; i < 4; i++) {
            int r = crow + i * 32;
            uint32_t da = sbase + (uint32_t)((r * TLDS + ccol) * 4);
            uint32_t db = sbase + (uint32_t)((TILE_F + r * TLDS + ccol) * 4);
            cp16(da, A + (long)(m0 + r) * ES + ccol);
            cp16(db, W + (long)(n0 + r) * ES + ccol);
        }
        cp_commit();
    }

    for (int kt = 0; kt < KT; kt++) {
        cp_wait0();
        __syncthreads();

        if (kt + 1 < KT) {
            const int k0 = (kt + 1) * TBK;
            const uint32_t boff = (uint32_t)(((kt + 1) & 1) * BUF_F * 4);
#pragma unroll
            for (int i = 0; i < 4; i++) {
                int r = crow + i * 32;
                uint32_t da = sbase + boff + (uint32_t)((r * TLDS + ccol) * 4);
                uint32_t db = sbase + boff + (uint32_t)((TILE_F + r * TLDS + ccol) * 4);
                cp16(da, A + (long)(m0 + r) * ES + k0 + ccol);
                cp16(db, W + (long)(n0 + r) * ES + k0 + ccol);
            }
            cp_commit();
        }

        const uint32_t off = (uint32_t)((kt & 1) * BUF_F * 4);
        const uint32_t aB = sbase + off +
            (uint32_t)(((wm * 32 + a_row_in) * TLDS + a_koff) * 4);
        const uint32_t bB = sbase + off +
            (uint32_t)((TILE_F + (wn * 64 + b_n_in) * TLDS + b_koff) * 4);

#pragma unroll
        for (int kk = 0; kk < 4; kk++) {
            uint32_t af[2][4], bf[8][2];
            LDSM4(af[0][0], af[0][1], af[0][2], af[0][3], aB + kk * 32);
            LDSM4(af[1][0], af[1][1], af[1][2], af[1][3],
                  aB + 16 * TLDS * 4 + kk * 32);
#pragma unroll
            for (int p = 0; p < 4; p++)
                LDSM4(bf[2 * p][0], bf[2 * p][1], bf[2 * p + 1][0], bf[2 * p + 1][1],
                      bB + p * 16 * TLDS * 4 + kk * 32);

#pragma unroll
            for (int mt = 0; mt < 2; mt++)
#pragma unroll
                for (int j = 0; j < 4; j++) af[mt][j] = f2tf32_u(af[mt][j]);
#pragma unroll
            for (int nt = 0; nt < 8; nt++) {
                bf[nt][0] = f2tf32_u(bf[nt][0]);
                bf[nt][1] = f2tf32_u(bf[nt][1]);
            }

#pragma unroll
            for (int mt = 0; mt < 2; mt++)
#pragma unroll
                for (int nt = 0; nt < 8; nt++)
                    mma_tf32(acc[mt][nt], af[mt], bf[nt]);
        }
        __syncthreads();
    }

    // ---- epilogue ----
    if (do_rope) {
        // col c = n0 + wn*64 + nt*8 + gc*2 ; within-head d = nt*8 + gc*2 (<32 for nt<4)
        // rotate-half: out[d] = x[d]*cos - x[d+32]*sin ; out[d+32] = x[d+32]*cos + x[d]*sin
#pragma unroll
        for (int mt = 0; mt < 2; mt++) {
            int r0g = m0 + wm * 32 + mt * 16 + gr;
            int l0 = r0g & (LS - 1);
            int l1 = (r0g + 8) & (LS - 1);
#pragma unroll
            for (int nt = 0; nt < 4; nt++) {
                int d = nt * 8 + gc * 2;
                float2 c0  = *(const float2*)(cosb + l0 * DH + d);
                float2 s0  = *(const float2*)(sinb + l0 * DH + d);
                float2 c0h = *(const float2*)(cosb + l0 * DH + d + 32);
                float2 s0h = *(const float2*)(sinb + l0 * DH + d + 32);
                float2 c1  = *(const float2*)(cosb + l1 * DH + d);
                float2 s1  = *(const float2*)(sinb + l1 * DH + d);
                float2 c1h = *(const float2*)(cosb + l1 * DH + d + 32);
                float2 s1h = *(const float2*)(sinb + l1 * DH + d + 32);

                const float* x1 = acc[mt][nt];
                const float* x2 = acc[mt][nt + 4];
                int cc = n0 + wn * 64 + nt * 8 + gc * 2;
                // row r0g
                *(float2*)(Cp + (long)r0g * ES + cc) =
                    make_float2(x1[0] * c0.x - x2[0] * s0.x,
                                x1[1] * c0.y - x2[1] * s0.y);
                *(float2*)(Cp + (long)r0g * ES + cc + 32) =
                    make_float2(x2[0] * c0h.x + x1[0] * s0h.x,
                                x2[1] * c0h.y + x1[1] * s0h.y);
                // row r0g+8
                *(float2*)(Cp + (long)(r0g + 8) * ES + cc) =
                    make_float2(x1[2] * c1.x - x2[2] * s1.x,
                                x1[3] * c1.y - x2[3] * s1.y);
                *(float2*)(Cp + (long)(r0g + 8) * ES + cc + 32) =
                    make_float2(x2[2] * c1h.x + x1[2] * s1h.x,
                                x2[3] * c1h.y + x1[3] * s1h.y);
            }
        }
    } else {
#pragma unroll
        for (int mt = 0; mt < 2; mt++) {
            int r0 = m0 + wm * 32 + mt * 16 + gr;
#pragma unroll
            for (int nt = 0; nt < 8; nt++) {
                int cc = n0 + wn * 64 + nt * 8 + gc * 2;
                *(float2*)(Cp + (long)r0 * ES + cc) =
                    make_float2(acc[mt][nt][0], acc[mt][nt][1]);
                *(float2*)(Cp + (long)(r0 + 8) * ES + cc) =
                    make_float2(acc[mt][nt][2], acc[mt][nt][3]);
            }
        }
    }
}

// fused QKV+rope: grid.z encodes proj in [0,3) and layer in [0,3)
__global__ __launch_bounds__(256, 2) void tf32_gemm_qkv(
    const float* __restrict__ x,
    const float* __restrict__ Wq, const float* __restrict__ Wk,
    const float* __restrict__ Wv,
    float* __restrict__ qb, float* __restrict__ kb, float* __restrict__ vb,
    const float* __restrict__ cosb, const float* __restrict__ sinb)
{
    extern __shared__ char smem[];
    const int z = blockIdx.z;
    const int proj  = z % 3;
    const int layer = z / 3;
    const float* W = (proj == 0 ? Wq : (proj == 1 ? Wk : Wv)) +
                     (long)layer * ES * ES;
    float* C = (proj == 0 ? qb : (proj == 1 ? kb : vb)) +
               (long)layer * LAYER_ELEMS;
    gemm_core(x, W, C, cosb, sinb, proj < 2 ? 1 : 0, smem);
}

__global__ __launch_bounds__(256, 2) void tf32_gemm_single(
    const float* __restrict__ A, const float* __restrict__ W,
    float* __restrict__ C)
{
    extern __shared__ char smem[];
    gemm_core(A, W, C, nullptr, nullptr, 0, smem);
}

// ---------------- Flash-style causal attention (fp32) ------------------------
__global__ __launch_bounds__(128) void flash_attn(
    const float* __restrict__ Q, const float* __restrict__ K,
    const float* __restrict__ V, float* __restrict__ O)
{
    extern __shared__ float sm[];
    float* QsT = sm;             // [d][row]
    float* KsT = sm + 4096;      // [d][col]
    float* Vs  = sm + 8192;      // [j][d]
    float* Ps  = sm + 12288;     // [row][65]

    const int qt = blockIdx.x;
    const int h  = blockIdx.y;
    const long base = (long)blockIdx.z * (LS * (long)ES);

    const int tid = threadIdx.x;
    const int tx = tid & 7;
    const int ty = tid >> 3;

    for (int i = tid; i < 1024; i += 128) {
        int row = i >> 4;
        int d   = (i & 15) << 2;
        float4 v = *(const float4*)(Q + base + (long)(qt * 64 + row) * ES + h * DH + d);
        QsT[(d + 0) * 64 + row] = v.x * ATT_SCALE;
        QsT[(d + 1) * 64 + row] = v.y * ATT_SCALE;
        QsT[(d + 2) * 64 + row] = v.z * ATT_SCALE;
        QsT[(d + 3) * 64 + row] = v.w * ATT_SCALE;
    }

    float m_i[4], l_i[4], acc[4][8];
#pragma unroll
    for (int r = 0; r < 4; r++) {
        m_i[r] = -1e30f; l_i[r] = 0.f;
#pragma unroll
        for (int c = 0; c < 8; c++) acc[r][c] = 0.f;
    }

    for (int kt = 0; kt <= qt; kt++) {
        __syncthreads();
        for (int i = tid; i < 1024; i += 128) {
            int row = i >> 4;
            int d   = (i & 15) << 2;
            long goff = base + (long)(kt * 64 + row) * ES + h * DH + d;
            float4 kv = *(const float4*)(K + goff);
            KsT[(d + 0) * 64 + row] = kv.x;
            KsT[(d + 1) * 64 + row] = kv.y;
            KsT[(d + 2) * 64 + row] = kv.z;
            KsT[(d + 3) * 64 + row] = kv.w;
            *(float4*)(Vs + row * 64 + d) = *(const float4*)(V + goff);
        }
        __syncthreads();

        float s[4][8];
#pragma unroll
        for (int r = 0; r < 4; r++)
#pragma unroll
            for (int c = 0; c < 8; c++) s[r][c] = 0.f;

#pragma unroll 4
        for (int d = 0; d < 64; d++) {
            float a[4], b[8];
            *(float4*)&a[0] = *(const float4*)&QsT[d * 64 + ty * 4];
            *(float4*)&b[0] = *(const float4*)&KsT[d * 64 + tx * 8];
            *(float4*)&b[4] = *(const float4*)&KsT[d * 64 + tx * 8 + 4];
#pragma unroll
            for (int r = 0; r < 4; r++)
#pragma unroll
                for (int c = 0; c < 8; c++)
                    s[r][c] = fmaf(a[r], b[c], s[r][c]);
        }

        if (kt == qt) {
#pragma unroll
            for (int r = 0; r < 4; r++)
#pragma unroll
                for (int c = 0; c < 8; c++)
                    if (tx * 8 + c > ty * 4 + r) s[r][c] = -1e30f;
        }

#pragma unroll
        for (int r = 0; r < 4; r++) {
            float mx = s[r][0];
#pragma unroll
            for (int c = 1; c < 8; c++) mx = fmaxf(mx, s[r][c]);
            mx = fmaxf(mx, __shfl_xor_sync(0xffffffffu, mx, 1));
            mx = fmaxf(mx, __shfl_xor_sync(0xffffffffu, mx, 2));
            mx = fmaxf(mx, __shfl_xor_sync(0xffffffffu, mx, 4));
            float mnew = fmaxf(m_i[r], mx);
            float f = __expf(m_i[r] - mnew);
            m_i[r] = mnew;
            float rs = 0.f;
#pragma unroll
            for (int c = 0; c < 8; c++) {
                float p = __expf(s[r][c] - mnew);
                s[r][c] = p;
                rs += p;
            }
            rs += __shfl_xor_sync(0xffffffffu, rs, 1);
            rs += __shfl_xor_sync(0xffffffffu, rs, 2);
            rs += __shfl_xor_sync(0xffffffffu, rs, 4);
            l_i[r] = l_i[r] * f + rs;
#pragma unroll
            for (int c = 0; c < 8; c++) acc[r][c] *= f;
#pragma unroll
            for (int c = 0; c < 8; c++)
                Ps[(ty * 4 + r) * 65 + tx * 8 + c] = s[r][c];
        }
        __syncthreads();

#pragma unroll 4
        for (int j = 0; j < 64; j++) {
            float bv[8];
            *(float4*)&bv[0] = *(const float4*)&Vs[j * 64 + tx * 8];
            *(float4*)&bv[4] = *(const float4*)&Vs[j * 64 + tx * 8 + 4];
#pragma unroll
            for (int r = 0; r < 4; r++) {
                float p = Ps[(ty * 4 + r) * 65 + j];
#pragma unroll
                for (int c = 0; c < 8; c++)
                    acc[r][c] = fmaf(p, bv[c], acc[r][c]);
            }
        }
    }

#pragma unroll
    for (int r = 0; r < 4; r++) {
        float inv = 1.f / l_i[r];
        long o = base + (long)(qt * 64 + ty * 4 + r) * ES + h * DH + tx * 8;
        O[o + 0] = acc[r][0] * inv; O[o + 1] = acc[r][1] * inv;
        O[o + 2] = acc[r][2] * inv; O[o + 3] = acc[r][3] * inv;
        O[o + 4] = acc[r][4] * inv; O[o + 5] = acc[r][5] * inv;
        O[o + 6] = acc[r][6] * inv; O[o + 7] = acc[r][7] * inv;
    }
}

// ---------------- per-row combine -------------------------------------------
__device__ __forceinline__ float blockSum256(float v)
{
    __shared__ float sh[8];
    __shared__ float total;
    int lane = threadIdx.x & 31, warp = threadIdx.x >> 5;
#pragma unroll
    for (int o = 16; o; o >>= 1) v += __shfl_xor_sync(0xffffffffu, v, o);
    __syncthreads();
    if (lane == 0) sh[warp] = v;
    __syncthreads();
    if (threadIdx.x == 0) {
        float t = 0.f;
#pragma unroll
        for (int i = 0; i < 8; i++) t += sh[i];
        total = t;
    }
    __syncthreads();
    return total;
}

__global__ __launch_bounds__(256) void combine_kernel(
    const float* __restrict__ A,
    const float* __restrict__ x,
    const float* __restrict__ g_ln,
    const float* __restrict__ lambdas,
    const float* __restrict__ g_final,
    const float* __restrict__ alpha,
    float* __restrict__ Y)
{
    const int row = blockIdx.x;
    const int tid = threadIdx.x;
    const int e0  = tid * 4;

    float sg0 = 1.f / (1.f + __expf(-lambdas[0]));
    float sg1 = 1.f / (1.f + __expf(-lambdas[1]));
    float sg2 = 1.f / (1.f + __expf(-lambdas[2]));
    float mu  = (sg0 + sg1 + sg2) * (1.f / 3.f);
    float va  = ((sg0 - mu) * (sg0 - mu) + (sg1 - mu) * (sg1 - mu) +
                 (sg2 - mu) * (sg2 - mu)) * (1.f / 3.f);
    float ivs = rsqrtf(va + EPSF);
    float lw0 = (sg0 - mu) * ivs, lw1 = (sg1 - mu) * ivs, lw2 = (sg2 - mu) * ivs;

    long ro = (long)row * ES + e0;
    float4 a0 = *(const float4*)(A + 0L * LAYER_ELEMS + ro);
    float4 a1 = *(const float4*)(A + 1L * LAYER_ELEMS + ro);
    float4 a2 = *(const float4*)(A + 2L * LAYER_ELEMS + ro);
    float4 xv = *(const float4*)(x + ro);

    float ss0 = blockSum256(a0.x*a0.x + a0.y*a0.y + a0.z*a0.z + a0.w*a0.w);
    float ss1 = blockSum256(a1.x*a1.x + a1.y*a1.y + a1.z*a1.z + a1.w*a1.w);
    float ss2 = blockSum256(a2.x*a2.x + a2.y*a2.y + a2.z*a2.z + a2.w*a2.w);

    float r0 = rsqrtf(ss0 * (1.f / ES) + EPSF) * lw0;
    float r1 = rsqrtf(ss1 * (1.f / ES) + EPSF) * lw1;
    float r2 = rsqrtf(ss2 * (1.f / ES) + EPSF) * lw2;
    float al = alpha[0];

    float4 g0 = *(const float4*)(g_ln + 0 * ES + e0);
    float4 g1 = *(const float4*)(g_ln + 1 * ES + e0);
    float4 g2 = *(const float4*)(g_ln + 2 * ES + e0);

    float4 cb;
    cb.x = a0.x*r0*g0.x + a1.x*r1*g1.x + a2.x*r2*g2.x + al*xv.x;
    cb.y = a0.y*r0*g0.y + a1.y*r1*g1.y + a2.y*r2*g2.y + al*xv.y;
    cb.z = a0.z*r0*g0.z + a1.z*r1*g1.z + a2.z*r2*g2.z + al*xv.z;
    cb.w = a0.w*r0*g0.w + a1.w*r1*g1.w + a2.w*r2*g2.w + al*xv.w;

    float ssc = blockSum256(cb.x*cb.x + cb.y*cb.y + cb.z*cb.z + cb.w*cb.w);
    float rc  = rsqrtf(ssc * (1.f / ES) + EPSF);

    float4 gf = *(const float4*)(g_final + e0);
    float4 yv;
    yv.x = cb.x * rc * gf.x; yv.y = cb.y * rc * gf.y;
    yv.z = cb.z * rc * gf.z; yv.w = cb.w * rc * gf.w;
    *(float4*)(Y + ro) = yv;
}

// ---------------- launch ------------------------------------------------------
extern "C" void kernel_launch(void* const* d_in, const int* in_sizes, int n_in,
                              void* d_out, int out_size)
{
    const float* x       = (const float*)d_in[0];
    const float* cosb    = (const float*)d_in[1];
    const float* sinb    = (const float*)d_in[2];
    // d_in[3] = attn_mask (pure causal; implemented directly)
    const float* Wq      = (const float*)d_in[4];
    const float* Wk      = (const float*)d_in[5];
    const float* Wv      = (const float*)d_in[6];
    const float* g_ln    = (const float*)d_in[7];
    const float* lambdas = (const float*)d_in[8];
    const float* Wo      = (const float*)d_in[9];
    const float* g_final = (const float*)d_in[10];
    const float* alpha   = (const float*)d_in[11];
    float* out = (float*)d_out;

    float *qb, *kb, *vb, *ab, *yb;
    cudaGetSymbolAddress((void**)&qb, d_QB);
    cudaGetSymbolAddress((void**)&kb, d_KB);
    cudaGetSymbolAddress((void**)&vb, d_VB);
    cudaGetSymbolAddress((void**)&ab, d_AB);
    cudaGetSymbolAddress((void**)&yb, d_YB);

    cudaFuncSetAttribute(tf32_gemm_qkv,
                         cudaFuncAttributeMaxDynamicSharedMemorySize, GEMM_SMEM);
    cudaFuncSetAttribute(tf32_gemm_single,
                         cudaFuncAttributeMaxDynamicSharedMemorySize, GEMM_SMEM);

    // 1) fused QKV projections + RoPE epilogue: 9 GEMMs in one launch
    dim3 gqkv(ES / TBN, MROWS / TBM, 9);
    tf32_gemm_qkv<<<gqkv, 256, GEMM_SMEM>>>(x, Wq, Wk, Wv, qb, kb, vb, cosb, sinb);

    // 2) flash attention over all (layer, batch, head, qtile)
    const int smem_bytes = (3 * 64 * 64 + 64 * 65) * 4;   // 65792
    cudaFuncSetAttribute(flash_attn, cudaFuncAttributeMaxDynamicSharedMemorySize,
                         smem_bytes);
    flash_attn<<<dim3(LS / 64, HH, NLAY * BB), 128, smem_bytes>>>(qb, kb, vb, ab);

    // 3) per-row norms + lambda combine + residual + final rmsnorm
    combine_kernel<<<MROWS, 256>>>(ab, x, g_ln, lambdas, g_final, alpha, yb);

    // 4) output projection
    tf32_gemm_single<<<dim3(ES / TBN, MROWS / TBM, 1), 256, GEMM_SMEM>>>(
        yb, Wo, out);
}

// round 12
// speedup vs baseline: 3.4530x; 1.8903x over previous
#include <cuda_runtime.h>
#include <cuda_bf16.h>
#include <cstdint>

// Problem constants
#define NLAY 3
#define BB   2
#define LS   1024
#define ES   1024
#define HH   16
#define DH   64
#define MROWS (BB*LS)              // 2048
#define LAYER_ELEMS (BB*LS*ES)     // 2097152
#define ATT_SCALE 0.125f           // D^-0.5 = 1/8
#define EPSF 1e-5f

// ---------------- scratch (static device allocations; no cudaMalloc) --------
__device__ float d_QB[NLAY * LAYER_ELEMS];
__device__ float d_KB[NLAY * LAYER_ELEMS];
__device__ float d_VT[NLAY * LAYER_ELEMS];   // V transposed: [lay][E][B*L]
__device__ float d_AB[NLAY * LAYER_ELEMS];
__device__ float d_YB[LAYER_ELEMS];

// =============================================================================
// Shared tf32 mma helpers
// =============================================================================
__device__ __forceinline__ uint32_t f2tf32_u(uint32_t bits) {
    uint32_t u;
    asm("cvt.rna.tf32.f32 %0, %1;" : "=r"(u) : "f"(__uint_as_float(bits)));
    return u;
}
__device__ __forceinline__ float tf32r(float x) {
    return __uint_as_float(f2tf32_u(__float_as_uint(x)));
}

__device__ __forceinline__ void mma_tf32(
    float c[4], const uint32_t a[4], const uint32_t b[2])
{
    asm volatile(
        "mma.sync.aligned.m16n8k8.row.col.f32.tf32.tf32.f32 "
        "{%0,%1,%2,%3}, {%4,%5,%6,%7}, {%8,%9}, {%0,%1,%2,%3};"
        : "+f"(c[0]), "+f"(c[1]), "+f"(c[2]), "+f"(c[3])
        : "r"(a[0]), "r"(a[1]), "r"(a[2]), "r"(a[3]),
          "r"(b[0]), "r"(b[1]));
}

__device__ __forceinline__ void cp16(uint32_t dst, const void* src) {
    asm volatile("cp.async.cg.shared.global [%0], [%1], 16;" :: "r"(dst), "l"(src));
}
__device__ __forceinline__ void cp_commit() {
    asm volatile("cp.async.commit_group;");
}
__device__ __forceinline__ void cp_wait0() {
    asm volatile("cp.async.wait_group 0;");
}

#define LDSM4(r0, r1, r2, r3, addr) \
    asm volatile("ldmatrix.sync.aligned.m8n8.x4.shared.b16 {%0,%1,%2,%3}, [%4];" \
                 : "=r"(r0), "=r"(r1), "=r"(r2), "=r"(r3) : "r"(addr))

// =============================================================================
// TF32 tensor-core GEMM: C = A @ W^T  (mode 0 = plain, 1 = fused RoPE,
// 2 = transposed store for V: Vt[col][row])
// =============================================================================
#define TBM 128
#define TBN 128
#define TBK 32
#define TLDS 36
#define TILE_F (TBM * TLDS)          // 4608 floats
#define BUF_F  (2 * TILE_F)          // 9216 floats (A+B)
#define GEMM_SMEM (2 * BUF_F * 4)    // 73728 bytes

__device__ __forceinline__ void gemm_core(
    const float* __restrict__ A, const float* __restrict__ W,
    float* __restrict__ Cp,
    const float* __restrict__ cosb, const float* __restrict__ sinb,
    int mode, char* smem)
{
    const int tid  = threadIdx.x;
    const int m0   = blockIdx.y * TBM;
    const int n0   = blockIdx.x * TBN;
    const int warp = tid >> 5, lane = tid & 31;
    const int wm = warp & 3;
    const int wn = warp >> 2;
    const int gr = lane >> 2;
    const int gc = lane & 3;

    const uint32_t sbase = (uint32_t)__cvta_generic_to_shared(smem);

    const int a_row_in = (lane & 7) + ((lane >> 3) & 1) * 8;
    const int a_koff   = (lane >> 4) * 4;
    const int b_n_in   = (lane & 7) + (lane >> 4) * 8;
    const int b_koff   = ((lane >> 3) & 1) * 4;

    const int crow = tid >> 3;
    const int ccol = (tid & 7) << 2;

    float acc[2][8][4];
#pragma unroll
    for (int mt = 0; mt < 2; mt++)
#pragma unroll
        for (int nt = 0; nt < 8; nt++)
#pragma unroll
            for (int c = 0; c < 4; c++) acc[mt][nt][c] = 0.f;

    const int KT = ES / TBK;

    {
#pragma unroll
        for (int i = 0; i < 4; i++) {
            int r = crow + i * 32;
            uint32_t da = sbase + (uint32_t)((r * TLDS + ccol) * 4);
            uint32_t db = sbase + (uint32_t)((TILE_F + r * TLDS + ccol) * 4);
            cp16(da, A + (long)(m0 + r) * ES + ccol);
            cp16(db, W + (long)(n0 + r) * ES + ccol);
        }
        cp_commit();
    }

    for (int kt = 0; kt < KT; kt++) {
        cp_wait0();
        __syncthreads();

        if (kt + 1 < KT) {
            const int k0 = (kt + 1) * TBK;
            const uint32_t boff = (uint32_t)(((kt + 1) & 1) * BUF_F * 4);
#pragma unroll
            for (int i = 0; i < 4; i++) {
                int r = crow + i * 32;
                uint32_t da = sbase + boff + (uint32_t)((r * TLDS + ccol) * 4);
                uint32_t db = sbase + boff + (uint32_t)((TILE_F + r * TLDS + ccol) * 4);
                cp16(da, A + (long)(m0 + r) * ES + k0 + ccol);
                cp16(db, W + (long)(n0 + r) * ES + k0 + ccol);
            }
            cp_commit();
        }

        const uint32_t off = (uint32_t)((kt & 1) * BUF_F * 4);
        const uint32_t aB = sbase + off +
            (uint32_t)(((wm * 32 + a_row_in) * TLDS + a_koff) * 4);
        const uint32_t bB = sbase + off +
            (uint32_t)((TILE_F + (wn * 64 + b_n_in) * TLDS + b_koff) * 4);

#pragma unroll
        for (int kk = 0; kk < 4; kk++) {
            uint32_t af[2][4], bf[8][2];
            LDSM4(af[0][0], af[0][1], af[0][2], af[0][3], aB + kk * 32);
            LDSM4(af[1][0], af[1][1], af[1][2], af[1][3],
                  aB + 16 * TLDS * 4 + kk * 32);
#pragma unroll
            for (int p = 0; p < 4; p++)
                LDSM4(bf[2 * p][0], bf[2 * p][1], bf[2 * p + 1][0], bf[2 * p + 1][1],
                      bB + p * 16 * TLDS * 4 + kk * 32);

#pragma unroll
            for (int mt = 0; mt < 2; mt++)
#pragma unroll
                for (int j = 0; j < 4; j++) af[mt][j] = f2tf32_u(af[mt][j]);
#pragma unroll
            for (int nt = 0; nt < 8; nt++) {
                bf[nt][0] = f2tf32_u(bf[nt][0]);
                bf[nt][1] = f2tf32_u(bf[nt][1]);
            }

#pragma unroll
            for (int mt = 0; mt < 2; mt++)
#pragma unroll
                for (int nt = 0; nt < 8; nt++)
                    mma_tf32(acc[mt][nt], af[mt], bf[nt]);
        }
        __syncthreads();
    }

    // ---- epilogue ----
    if (mode == 1) {
        // fused RoPE (rotate_half): pair (d, d+32) lives in (nt, nt+4)
#pragma unroll
        for (int mt = 0; mt < 2; mt++) {
            int r0g = m0 + wm * 32 + mt * 16 + gr;
            int l0 = r0g & (LS - 1);
            int l1 = (r0g + 8) & (LS - 1);
#pragma unroll
            for (int nt = 0; nt < 4; nt++) {
                int d = nt * 8 + gc * 2;
                float2 c0  = *(const float2*)(cosb + l0 * DH + d);
                float2 s0  = *(const float2*)(sinb + l0 * DH + d);
                float2 c0h = *(const float2*)(cosb + l0 * DH + d + 32);
                float2 s0h = *(const float2*)(sinb + l0 * DH + d + 32);
                float2 c1  = *(const float2*)(cosb + l1 * DH + d);
                float2 s1  = *(const float2*)(sinb + l1 * DH + d);
                float2 c1h = *(const float2*)(cosb + l1 * DH + d + 32);
                float2 s1h = *(const float2*)(sinb + l1 * DH + d + 32);

                const float* x1 = acc[mt][nt];
                const float* x2 = acc[mt][nt + 4];
                int cc = n0 + wn * 64 + nt * 8 + gc * 2;
                *(float2*)(Cp + (long)r0g * ES + cc) =
                    make_float2(x1[0] * c0.x - x2[0] * s0.x,
                                x1[1] * c0.y - x2[1] * s0.y);
                *(float2*)(Cp + (long)r0g * ES + cc + 32) =
                    make_float2(x2[0] * c0h.x + x1[0] * s0h.x,
                                x2[1] * c0h.y + x1[1] * s0h.y);
                *(float2*)(Cp + (long)(r0g + 8) * ES + cc) =
                    make_float2(x1[2] * c1.x - x2[2] * s1.x,
                                x1[3] * c1.y - x2[3] * s1.y);
                *(float2*)(Cp + (long)(r0g + 8) * ES + cc + 32) =
                    make_float2(x2[2] * c1h.x + x1[2] * s1h.x,
                                x2[3] * c1h.y + x1[3] * s1h.y);
            }
        }
    } else if (mode == 2) {
        // transposed store: Vt[col][row], row-length MROWS
#pragma unroll
        for (int mt = 0; mt < 2; mt++) {
            int r0 = m0 + wm * 32 + mt * 16 + gr;
#pragma unroll
            for (int nt = 0; nt < 8; nt++) {
                int cc = n0 + wn * 64 + nt * 8 + gc * 2;
                Cp[(long)cc * MROWS + r0]           = acc[mt][nt][0];
                Cp[(long)(cc + 1) * MROWS + r0]     = acc[mt][nt][1];
                Cp[(long)cc * MROWS + r0 + 8]       = acc[mt][nt][2];
                Cp[(long)(cc + 1) * MROWS + r0 + 8] = acc[mt][nt][3];
            }
        }
    } else {
#pragma unroll
        for (int mt = 0; mt < 2; mt++) {
            int r0 = m0 + wm * 32 + mt * 16 + gr;
#pragma unroll
            for (int nt = 0; nt < 8; nt++) {
                int cc = n0 + wn * 64 + nt * 8 + gc * 2;
                *(float2*)(Cp + (long)r0 * ES + cc) =
                    make_float2(acc[mt][nt][0], acc[mt][nt][1]);
                *(float2*)(Cp + (long)(r0 + 8) * ES + cc) =
                    make_float2(acc[mt][nt][2], acc[mt][nt][3]);
            }
        }
    }
}

// fused QKV+rope: grid.z encodes proj in [0,3) and layer in [0,3)
__global__ __launch_bounds__(256, 2) void tf32_gemm_qkv(
    const float* __restrict__ x,
    const float* __restrict__ Wq, const float* __restrict__ Wk,
    const float* __restrict__ Wv,
    float* __restrict__ qb, float* __restrict__ kb, float* __restrict__ vt,
    const float* __restrict__ cosb, const float* __restrict__ sinb)
{
    extern __shared__ char smem[];
    const int z = blockIdx.z;
    const int proj  = z % 3;
    const int layer = z / 3;
    const float* W = (proj == 0 ? Wq : (proj == 1 ? Wk : Wv)) +
                     (long)layer * ES * ES;
    float* C = (proj == 0 ? qb : (proj == 1 ? kb : vt)) +
               (long)layer * LAYER_ELEMS;
    gemm_core(x, W, C, cosb, sinb, proj == 2 ? 2 : 1, smem);
}

__global__ __launch_bounds__(256, 2) void tf32_gemm_single(
    const float* __restrict__ A, const float* __restrict__ W,
    float* __restrict__ C)
{
    extern __shared__ char smem[];
    gemm_core(A, W, C, nullptr, nullptr, 0, smem);
}

// =============================================================================
// Flash attention on tensor cores.
// Block = 128 thr (4 warps), one (qt, h, z) tile of 64 queries.
// S = QK^T in 3xTF32 (Q,K split hi/lo at smem load), PV in 1x tf32.
// Smem: Qh,Ql,Kh,Kl,VsT,Ps each [64][68] fp32.
// =============================================================================
#define ASTR 68
#define AQH  0
#define AQL  (64*ASTR)
#define AKH  (2*64*ASTR)
#define AKL  (3*64*ASTR)
#define AVT  (4*64*ASTR)
#define APS  (5*64*ASTR)
#define ATT_SMEM (6*64*ASTR*4)       // 104448 bytes

__global__ __launch_bounds__(128) void flash_attn_mma(
    const float* __restrict__ Q, const float* __restrict__ K,
    const float* __restrict__ Vt, float* __restrict__ O)
{
    extern __shared__ float sm[];
    const int qt = (int)(gridDim.x - 1 - blockIdx.x);  // big tiles first
    const int h  = blockIdx.y;
    const int z  = blockIdx.z;
    const long baseqk = (long)z * (LS * (long)ES);
    const int lay = z >> 1, bbi = z & 1;
    const long basev = ((long)lay * ES + h * DH) * (long)MROWS + bbi * LS;

    const int tid  = threadIdx.x;
    const int warp = tid >> 5, lane = tid & 31;
    const int gr = lane >> 2, gc = lane & 3;
    const int a_row_in = (lane & 7) + ((lane >> 3) & 1) * 8;
    const int a_koff   = (lane >> 4) * 4;
    const int b_n_in   = (lane & 7) + (lane >> 4) * 8;
    const int b_koff   = ((lane >> 3) & 1) * 4;

    const uint32_t sb = (uint32_t)__cvta_generic_to_shared(sm);

    // ---- load Q once: scale, split hi/lo tf32 ----
#pragma unroll
    for (int i = 0; i < 8; i++) {
        int idx = tid + i * 128;
        int row = idx >> 4, d4 = (idx & 15) << 2;
        float4 v = *(const float4*)(Q + baseqk + (long)(qt * 64 + row) * ES +
                                    h * DH + d4);
        v.x *= ATT_SCALE; v.y *= ATT_SCALE; v.z *= ATT_SCALE; v.w *= ATT_SCALE;
        float4 hi, lo;
        hi.x = tf32r(v.x); lo.x = tf32r(v.x - hi.x);
        hi.y = tf32r(v.y); lo.y = tf32r(v.y - hi.y);
        hi.z = tf32r(v.z); lo.z = tf32r(v.z - hi.z);
        hi.w = tf32r(v.w); lo.w = tf32r(v.w - hi.w);
        *(float4*)(sm + AQH + row * ASTR + d4) = hi;
        *(float4*)(sm + AQL + row * ASTR + d4) = lo;
    }

    float o[8][4];
#pragma unroll
    for (int nt = 0; nt < 8; nt++)
#pragma unroll
        for (int c = 0; c < 4; c++) o[nt][c] = 0.f;
    float m0 = -1e30f, m1 = -1e30f, l0 = 0.f, l1 = 0.f;

    const uint32_t qhB = sb + (uint32_t)((AQH + (warp * 16 + a_row_in) * ASTR + a_koff) * 4);
    const uint32_t qlB = sb + (uint32_t)((AQL + (warp * 16 + a_row_in) * ASTR + a_koff) * 4);
    const uint32_t khB = sb + (uint32_t)((AKH + b_n_in * ASTR + b_koff) * 4);
    const uint32_t klB = sb + (uint32_t)((AKL + b_n_in * ASTR + b_koff) * 4);
    const uint32_t psB = sb + (uint32_t)((APS + (warp * 16 + a_row_in) * ASTR + a_koff) * 4);
    const uint32_t vtB = sb + (uint32_t)((AVT + b_n_in * ASTR + b_koff) * 4);

    for (int kt = 0; kt <= qt; kt++) {
        __syncthreads();   // prev tile fully consumed before overwrite (also Q first iter)
#pragma unroll
        for (int i = 0; i < 8; i++) {
            int idx = tid + i * 128;
            int row = idx >> 4, d4 = (idx & 15) << 2;
            float4 kv = *(const float4*)(K + baseqk + (long)(kt * 64 + row) * ES +
                                         h * DH + d4);
            float4 hi, lo;
            hi.x = tf32r(kv.x); lo.x = tf32r(kv.x - hi.x);
            hi.y = tf32r(kv.y); lo.y = tf32r(kv.y - hi.y);
            hi.z = tf32r(kv.z); lo.z = tf32r(kv.z - hi.z);
            hi.w = tf32r(kv.w); lo.w = tf32r(kv.w - hi.w);
            *(float4*)(sm + AKH + row * ASTR + d4) = hi;
            *(float4*)(sm + AKL + row * ASTR + d4) = lo;
            // V^T tile: row = d, d4 = kv offset (straight copy, pre-cvt)
            float4 vv = *(const float4*)(Vt + basev + (long)row * MROWS +
                                         kt * 64 + d4);
            vv.x = tf32r(vv.x); vv.y = tf32r(vv.y);
            vv.z = tf32r(vv.z); vv.w = tf32r(vv.w);
            *(float4*)(sm + AVT + row * ASTR + d4) = vv;
        }
        __syncthreads();

        // ---- S = Q K^T (3xTF32) ----
        float s[8][4];
#pragma unroll
        for (int nt = 0; nt < 8; nt++)
#pragma unroll
            for (int c = 0; c < 4; c++) s[nt][c] = 0.f;

#pragma unroll
        for (int kk = 0; kk < 8; kk++) {
            uint32_t qh[4], ql[4], kh[8][2], kl[8][2];
            LDSM4(qh[0], qh[1], qh[2], qh[3], qhB + kk * 32);
            LDSM4(ql[0], ql[1], ql[2], ql[3], qlB + kk * 32);
#pragma unroll
            for (int p = 0; p < 4; p++) {
                LDSM4(kh[2*p][0], kh[2*p][1], kh[2*p+1][0], kh[2*p+1][1],
                      khB + p * 16 * ASTR * 4 + kk * 32);
                LDSM4(kl[2*p][0], kl[2*p][1], kl[2*p+1][0], kl[2*p+1][1],
                      klB + p * 16 * ASTR * 4 + kk * 32);
            }
#pragma unroll
            for (int nt = 0; nt < 8; nt++) {
                mma_tf32(s[nt], qh, kh[nt]);
                mma_tf32(s[nt], ql, kh[nt]);
                mma_tf32(s[nt], qh, kl[nt]);
            }
        }

        if (kt == qt) {   // diagonal: causal mask within tile
            int r0 = warp * 16 + gr, r1 = r0 + 8;
#pragma unroll
            for (int nt = 0; nt < 8; nt++) {
                int c0 = nt * 8 + 2 * gc;
                if (c0 > r0)     s[nt][0] = -1e30f;
                if (c0 + 1 > r0) s[nt][1] = -1e30f;
                if (c0 > r1)     s[nt][2] = -1e30f;
                if (c0 + 1 > r1) s[nt][3] = -1e30f;
            }
        }

        // ---- online softmax ----
        float mx0 = -1e30f, mx1 = -1e30f;
#pragma unroll
        for (int nt = 0; nt < 8; nt++) {
            mx0 = fmaxf(mx0, fmaxf(s[nt][0], s[nt][1]));
            mx1 = fmaxf(mx1, fmaxf(s[nt][2], s[nt][3]));
        }
        mx0 = fmaxf(mx0, __shfl_xor_sync(0xffffffffu, mx0, 1));
        mx0 = fmaxf(mx0, __shfl_xor_sync(0xffffffffu, mx0, 2));
        mx1 = fmaxf(mx1, __shfl_xor_sync(0xffffffffu, mx1, 1));
        mx1 = fmaxf(mx1, __shfl_xor_sync(0xffffffffu, mx1, 2));

        float m0n = fmaxf(m0, mx0), m1n = fmaxf(m1, mx1);
        float f0 = __expf(m0 - m0n), f1 = __expf(m1 - m1n);
        m0 = m0n; m1 = m1n;

        float rs0 = 0.f, rs1 = 0.f;
        int pr0 = warp * 16 + gr;
#pragma unroll
        for (int nt = 0; nt < 8; nt++) {
            float p0 = __expf(s[nt][0] - m0n);
            float p1 = __expf(s[nt][1] - m0n);
            float p2 = __expf(s[nt][2] - m1n);
            float p3 = __expf(s[nt][3] - m1n);
            rs0 += p0 + p1; rs1 += p2 + p3;
            *(float2*)(sm + APS + pr0 * ASTR + nt * 8 + 2 * gc) =
                make_float2(tf32r(p0), tf32r(p1));
            *(float2*)(sm + APS + (pr0 + 8) * ASTR + nt * 8 + 2 * gc) =
                make_float2(tf32r(p2), tf32r(p3));
            o[nt][0] *= f0; o[nt][1] *= f0; o[nt][2] *= f1; o[nt][3] *= f1;
        }
        rs0 += __shfl_xor_sync(0xffffffffu, rs0, 1);
        rs0 += __shfl_xor_sync(0xffffffffu, rs0, 2);
        rs1 += __shfl_xor_sync(0xffffffffu, rs1, 1);
        rs1 += __shfl_xor_sync(0xffffffffu, rs1, 2);
        l0 = l0 * f0 + rs0;
        l1 = l1 * f1 + rs1;
        __syncwarp();   // Ps stores visible to own warp's ldmatrix

        // ---- O += P V (1x tf32) ----
#pragma unroll
        for (int kk = 0; kk < 8; kk++) {
            uint32_t pf[4], vf[8][2];
            LDSM4(pf[0], pf[1], pf[2], pf[3], psB + kk * 32);
#pragma unroll
            for (int p = 0; p < 4; p++)
                LDSM4(vf[2*p][0], vf[2*p][1], vf[2*p+1][0], vf[2*p+1][1],
                      vtB + p * 16 * ASTR * 4 + kk * 32);
#pragma unroll
            for (int nt = 0; nt < 8; nt++)
                mma_tf32(o[nt], pf, vf[nt]);
        }
    }

    // ---- epilogue ----
    float i0 = 1.f / l0, i1 = 1.f / l1;
    int r0 = qt * 64 + warp * 16 + gr;
#pragma unroll
    for (int nt = 0; nt < 8; nt++) {
        int cc = h * DH + nt * 8 + 2 * gc;
        *(float2*)(O + baseqk + (long)r0 * ES + cc) =
            make_float2(o[nt][0] * i0, o[nt][1] * i0);
        *(float2*)(O + baseqk + (long)(r0 + 8) * ES + cc) =
            make_float2(o[nt][2] * i1, o[nt][3] * i1);
    }
}

// ---------------- per-row combine -------------------------------------------
__device__ __forceinline__ float blockSum256(float v)
{
    __shared__ float sh[8];
    __shared__ float total;
    int lane = threadIdx.x & 31, warp = threadIdx.x >> 5;
#pragma unroll
    for (int oo = 16; oo; oo >>= 1) v += __shfl_xor_sync(0xffffffffu, v, oo);
    __syncthreads();
    if (lane == 0) sh[warp] = v;
    __syncthreads();
    if (threadIdx.x == 0) {
        float t = 0.f;
#pragma unroll
        for (int i = 0; i < 8; i++) t += sh[i];
        total = t;
    }
    __syncthreads();
    return total;
}

__global__ __launch_bounds__(256) void combine_kernel(
    const float* __restrict__ A,
    const float* __restrict__ x,
    const float* __restrict__ g_ln,
    const float* __restrict__ lambdas,
    const float* __restrict__ g_final,
    const float* __restrict__ alpha,
    float* __restrict__ Y)
{
    const int row = blockIdx.x;
    const int tid = threadIdx.x;
    const int e0  = tid * 4;

    float sg0 = 1.f / (1.f + __expf(-lambdas[0]));
    float sg1 = 1.f / (1.f + __expf(-lambdas[1]));
    float sg2 = 1.f / (1.f + __expf(-lambdas[2]));
    float mu  = (sg0 + sg1 + sg2) * (1.f / 3.f);
    float va  = ((sg0 - mu) * (sg0 - mu) + (sg1 - mu) * (sg1 - mu) +
                 (sg2 - mu) * (sg2 - mu)) * (1.f / 3.f);
    float ivs = rsqrtf(va + EPSF);
    float lw0 = (sg0 - mu) * ivs, lw1 = (sg1 - mu) * ivs, lw2 = (sg2 - mu) * ivs;

    long ro = (long)row * ES + e0;
    float4 a0 = *(const float4*)(A + 0L * LAYER_ELEMS + ro);
    float4 a1 = *(const float4*)(A + 1L * LAYER_ELEMS + ro);
    float4 a2 = *(const float4*)(A + 2L * LAYER_ELEMS + ro);
    float4 xv = *(const float4*)(x + ro);

    float ss0 = blockSum256(a0.x*a0.x + a0.y*a0.y + a0.z*a0.z + a0.w*a0.w);
    float ss1 = blockSum256(a1.x*a1.x + a1.y*a1.y + a1.z*a1.z + a1.w*a1.w);
    float ss2 = blockSum256(a2.x*a2.x + a2.y*a2.y + a2.z*a2.z + a2.w*a2.w);

    float r0 = rsqrtf(ss0 * (1.f / ES) + EPSF) * lw0;
    float r1 = rsqrtf(ss1 * (1.f / ES) + EPSF) * lw1;
    float r2 = rsqrtf(ss2 * (1.f / ES) + EPSF) * lw2;
    float al = alpha[0];

    float4 g0 = *(const float4*)(g_ln + 0 * ES + e0);
    float4 g1 = *(const float4*)(g_ln + 1 * ES + e0);
    float4 g2 = *(const float4*)(g_ln + 2 * ES + e0);

    float4 cb;
    cb.x = a0.x*r0*g0.x + a1.x*r1*g1.x + a2.x*r2*g2.x + al*xv.x;
    cb.y = a0.y*r0*g0.y + a1.y*r1*g1.y + a2.y*r2*g2.y + al*xv.y;
    cb.z = a0.z*r0*g0.z + a1.z*r1*g1.z + a2.z*r2*g2.z + al*xv.z;
    cb.w = a0.w*r0*g0.w + a1.w*r1*g1.w + a2.w*r2*g2.w + al*xv.w;

    float ssc = blockSum256(cb.x*cb.x + cb.y*cb.y + cb.z*cb.z + cb.w*cb.w);
    float rc  = rsqrtf(ssc * (1.f / ES) + EPSF);

    float4 gf = *(const float4*)(g_final + e0);
    float4 yv;
    yv.x = cb.x * rc * gf.x; yv.y = cb.y * rc * gf.y;
    yv.z = cb.z * rc * gf.z; yv.w = cb.w * rc * gf.w;
    *(float4*)(Y + ro) = yv;
}

// ---------------- launch ------------------------------------------------------
extern "C" void kernel_launch(void* const* d_in, const int* in_sizes, int n_in,
                              void* d_out, int out_size)
{
    const float* x       = (const float*)d_in[0];
    const float* cosb    = (const float*)d_in[1];
    const float* sinb    = (const float*)d_in[2];
    // d_in[3] = attn_mask (pure causal; implemented directly)
    const float* Wq      = (const float*)d_in[4];
    const float* Wk      = (const float*)d_in[5];
    const float* Wv      = (const float*)d_in[6];
    const float* g_ln    = (const float*)d_in[7];
    const float* lambdas = (const float*)d_in[8];
    const float* Wo      = (const float*)d_in[9];
    const float* g_final = (const float*)d_in[10];
    const float* alpha   = (const float*)d_in[11];
    float* out = (float*)d_out;

    float *qb, *kb, *vt, *ab, *yb;
    cudaGetSymbolAddress((void**)&qb, d_QB);
    cudaGetSymbolAddress((void**)&kb, d_KB);
    cudaGetSymbolAddress((void**)&vt, d_VT);
    cudaGetSymbolAddress((void**)&ab, d_AB);
    cudaGetSymbolAddress((void**)&yb, d_YB);

    cudaFuncSetAttribute(tf32_gemm_qkv,
                         cudaFuncAttributeMaxDynamicSharedMemorySize, GEMM_SMEM);
    cudaFuncSetAttribute(tf32_gemm_single,
                         cudaFuncAttributeMaxDynamicSharedMemorySize, GEMM_SMEM);
    cudaFuncSetAttribute(flash_attn_mma,
                         cudaFuncAttributeMaxDynamicSharedMemorySize, ATT_SMEM);

    // 1) fused QKV projections (+RoPE on Q/K, transposed store for V)
    dim3 gqkv(ES / TBN, MROWS / TBM, 9);
    tf32_gemm_qkv<<<gqkv, 256, GEMM_SMEM>>>(x, Wq, Wk, Wv, qb, kb, vt, cosb, sinb);

    // 2) tensor-core flash attention
    flash_attn_mma<<<dim3(LS / 64, HH, NLAY * BB), 128, ATT_SMEM>>>(qb, kb, vt, ab);

    // 3) per-row norms + lambda combine + residual + final rmsnorm
    combine_kernel<<<MROWS, 256>>>(ab, x, g_ln, lambdas, g_final, alpha, yb);

    // 4) output projection
    tf32_gemm_single<<<dim3(ES / TBN, MROWS / TBM, 1), 256, GEMM_SMEM>>>(
        yb, Wo, out);
}

// round 14
// speedup vs baseline: 3.6230x; 1.0492x over previous
#include <cuda_runtime.h>
#include <cuda_bf16.h>
#include <cstdint>

// Problem constants
#define NLAY 3
#define BB   2
#define LS   1024
#define ES   1024
#define HH   16
#define DH   64
#define MROWS (BB*LS)              // 2048
#define LAYER_ELEMS (BB*LS*ES)     // 2097152
#define ATT_SCALE 0.125f           // D^-0.5 = 1/8
#define EPSF 1e-5f

// ---------------- scratch (static device allocations; no cudaMalloc) --------
__device__ float d_QB[NLAY * LAYER_ELEMS];
__device__ float d_KB[NLAY * LAYER_ELEMS];
__device__ float d_VT[NLAY * LAYER_ELEMS];   // V transposed: [lay][E][B*L]
__device__ float d_AB[NLAY * LAYER_ELEMS];
__device__ float d_YB[LAYER_ELEMS];
// pre-rounded (tf32-valued fp32) copies of GEMM inputs
__device__ float d_XR[LAYER_ELEMS];
__device__ float d_WQR[NLAY * ES * ES];
__device__ float d_WKR[NLAY * ES * ES];
__device__ float d_WVR[NLAY * ES * ES];
__device__ float d_WOR[ES * ES];

// =============================================================================
// Shared tf32 mma helpers
// =============================================================================
__device__ __forceinline__ uint32_t f2tf32_u(uint32_t bits) {
    uint32_t u;
    asm("cvt.rna.tf32.f32 %0, %1;" : "=r"(u) : "f"(__uint_as_float(bits)));
    return u;
}
__device__ __forceinline__ float tf32r(float x) {
    return __uint_as_float(f2tf32_u(__float_as_uint(x)));
}

__device__ __forceinline__ void mma_tf32(
    float c[4], const uint32_t a[4], const uint32_t b[2])
{
    asm volatile(
        "mma.sync.aligned.m16n8k8.row.col.f32.tf32.tf32.f32 "
        "{%0,%1,%2,%3}, {%4,%5,%6,%7}, {%8,%9}, {%0,%1,%2,%3};"
        : "+f"(c[0]), "+f"(c[1]), "+f"(c[2]), "+f"(c[3])
        : "r"(a[0]), "r"(a[1]), "r"(a[2]), "r"(a[3]),
          "r"(b[0]), "r"(b[1]));
}

__device__ __forceinline__ void cp16(uint32_t dst, const void* src) {
    asm volatile("cp.async.cg.shared.global [%0], [%1], 16;" :: "r"(dst), "l"(src));
}
__device__ __forceinline__ void cp_commit() {
    asm volatile("cp.async.commit_group;");
}
__device__ __forceinline__ void cp_wait0() {
    asm volatile("cp.async.wait_group 0;");
}

#define LDSM4(r0, r1, r2, r3, addr) \
    asm volatile("ldmatrix.sync.aligned.m8n8.x4.shared.b16 {%0,%1,%2,%3}, [%4];" \
                 : "=r"(r0), "=r"(r1), "=r"(r2), "=r"(r3) : "r"(addr))

// ---------------- pre-round kernel: dst = tf32_rna(src), vectorized ----------
__global__ void preround_kernel(const float* __restrict__ src,
                                float* __restrict__ dst, int n4)
{
    int i = blockIdx.x * blockDim.x + threadIdx.x;
    if (i >= n4) return;
    float4 v = ((const float4*)src)[i];
    v.x = tf32r(v.x); v.y = tf32r(v.y); v.z = tf32r(v.z); v.w = tf32r(v.w);
    ((float4*)dst)[i] = v;
}

// =============================================================================
// TF32 tensor-core GEMM: C = A @ W^T  (mode 0 = plain, 1 = fused RoPE,
// 2 = transposed store for V: Vt[col][row])
// Inputs MUST be pre-rounded to tf32-valued fp32 (no in-loop cvt).
// =============================================================================
#define TBM 128
#define TBN 128
#define TBK 32
#define TLDS 36
#define TILE_F (TBM * TLDS)          // 4608 floats
#define BUF_F  (2 * TILE_F)          // 9216 floats (A+B)
#define GEMM_SMEM (2 * BUF_F * 4)    // 73728 bytes

__device__ __forceinline__ void gemm_core(
    const float* __restrict__ A, const float* __restrict__ W,
    float* __restrict__ Cp,
    const float* __restrict__ cosb, const float* __restrict__ sinb,
    int mode, char* smem)
{
    const int tid  = threadIdx.x;
    const int m0   = blockIdx.y * TBM;
    const int n0   = blockIdx.x * TBN;
    const int warp = tid >> 5, lane = tid & 31;
    const int wm = warp & 3;
    const int wn = warp >> 2;
    const int gr = lane >> 2;
    const int gc = lane & 3;

    const uint32_t sbase = (uint32_t)__cvta_generic_to_shared(smem);

    const int a_row_in = (lane & 7) + ((lane >> 3) & 1) * 8;
    const int a_koff   = (lane >> 4) * 4;
    const int b_n_in   = (lane & 7) + (lane >> 4) * 8;
    const int b_koff   = ((lane >> 3) & 1) * 4;

    const int crow = tid >> 3;
    const int ccol = (tid & 7) << 2;

    float acc[2][8][4];
#pragma unroll
    for (int mt = 0; mt < 2; mt++)
#pragma unroll
        for (int nt = 0; nt < 8; nt++)
#pragma unroll
            for (int c = 0; c < 4; c++) acc[mt][nt][c] = 0.f;

    const int KT = ES / TBK;

    {
#pragma unroll
        for (int i = 0; i < 4; i++) {
            int r = crow + i * 32;
            uint32_t da = sbase + (uint32_t)((r * TLDS + ccol) * 4);
            uint32_t db = sbase + (uint32_t)((TILE_F + r * TLDS + ccol) * 4);
            cp16(da, A + (long)(m0 + r) * ES + ccol);
            cp16(db, W + (long)(n0 + r) * ES + ccol);
        }
        cp_commit();
    }

    for (int kt = 0; kt < KT; kt++) {
        cp_wait0();
        __syncthreads();

        if (kt + 1 < KT) {
            const int k0 = (kt + 1) * TBK;
            const uint32_t boff = (uint32_t)(((kt + 1) & 1) * BUF_F * 4);
#pragma unroll
            for (int i = 0; i < 4; i++) {
                int r = crow + i * 32;
                uint32_t da = sbase + boff + (uint32_t)((r * TLDS + ccol) * 4);
                uint32_t db = sbase + boff + (uint32_t)((TILE_F + r * TLDS + ccol) * 4);
                cp16(da, A + (long)(m0 + r) * ES + k0 + ccol);
                cp16(db, W + (long)(n0 + r) * ES + k0 + ccol);
            }
            cp_commit();
        }

        const uint32_t off = (uint32_t)((kt & 1) * BUF_F * 4);
        const uint32_t aB = sbase + off +
            (uint32_t)(((wm * 32 + a_row_in) * TLDS + a_koff) * 4);
        const uint32_t bB = sbase + off +
            (uint32_t)((TILE_F + (wn * 64 + b_n_in) * TLDS + b_koff) * 4);

#pragma unroll
        for (int kk = 0; kk < 4; kk++) {
            uint32_t af[2][4], bf[8][2];
            LDSM4(af[0][0], af[0][1], af[0][2], af[0][3], aB + kk * 32);
            LDSM4(af[1][0], af[1][1], af[1][2], af[1][3],
                  aB + 16 * TLDS * 4 + kk * 32);
#pragma unroll
            for (int p = 0; p < 4; p++)
                LDSM4(bf[2 * p][0], bf[2 * p][1], bf[2 * p + 1][0], bf[2 * p + 1][1],
                      bB + p * 16 * TLDS * 4 + kk * 32);

#pragma unroll
            for (int mt = 0; mt < 2; mt++)
#pragma unroll
                for (int nt = 0; nt < 8; nt++)
                    mma_tf32(acc[mt][nt], af[mt], bf[nt]);
        }
        __syncthreads();
    }

    // ---- epilogue ----
    if (mode == 1) {
        // fused RoPE (rotate_half): pair (d, d+32) lives in (nt, nt+4)
#pragma unroll
        for (int mt = 0; mt < 2; mt++) {
            int r0g = m0 + wm * 32 + mt * 16 + gr;
            int l0 = r0g & (LS - 1);
            int l1 = (r0g + 8) & (LS - 1);
#pragma unroll
            for (int nt = 0; nt < 4; nt++) {
                int d = nt * 8 + gc * 2;
                float2 c0  = *(const float2*)(cosb + l0 * DH + d);
                float2 s0  = *(const float2*)(sinb + l0 * DH + d);
                float2 c0h = *(const float2*)(cosb + l0 * DH + d + 32);
                float2 s0h = *(const float2*)(sinb + l0 * DH + d + 32);
                float2 c1  = *(const float2*)(cosb + l1 * DH + d);
                float2 s1  = *(const float2*)(sinb + l1 * DH + d);
                float2 c1h = *(const float2*)(cosb + l1 * DH + d + 32);
                float2 s1h = *(const float2*)(sinb + l1 * DH + d + 32);

                const float* x1 = acc[mt][nt];
                const float* x2 = acc[mt][nt + 4];
                int cc = n0 + wn * 64 + nt * 8 + gc * 2;
                *(float2*)(Cp + (long)r0g * ES + cc) =
                    make_float2(x1[0] * c0.x - x2[0] * s0.x,
                                x1[1] * c0.y - x2[1] * s0.y);
                *(float2*)(Cp + (long)r0g * ES + cc + 32) =
                    make_float2(x2[0] * c0h.x + x1[0] * s0h.x,
                                x2[1] * c0h.y + x1[1] * s0h.y);
                *(float2*)(Cp + (long)(r0g + 8) * ES + cc) =
                    make_float2(x1[2] * c1.x - x2[2] * s1.x,
                                x1[3] * c1.y - x2[3] * s1.y);
                *(float2*)(Cp + (long)(r0g + 8) * ES + cc + 32) =
                    make_float2(x2[2] * c1h.x + x1[2] * s1h.x,
                                x2[3] * c1h.y + x1[3] * s1h.y);
            }
        }
    } else if (mode == 2) {
        // transposed store: Vt[col][row], row-length MROWS
#pragma unroll
        for (int mt = 0; mt < 2; mt++) {
            int r0 = m0 + wm * 32 + mt * 16 + gr;
#pragma unroll
            for (int nt = 0; nt < 8; nt++) {
                int cc = n0 + wn * 64 + nt * 8 + gc * 2;
                Cp[(long)cc * MROWS + r0]           = acc[mt][nt][0];
                Cp[(long)(cc + 1) * MROWS + r0]     = acc[mt][nt][1];
                Cp[(long)cc * MROWS + r0 + 8]       = acc[mt][nt][2];
                Cp[(long)(cc + 1) * MROWS + r0 + 8] = acc[mt][nt][3];
            }
        }
    } else {
#pragma unroll
        for (int mt = 0; mt < 2; mt++) {
            int r0 = m0 + wm * 32 + mt * 16 + gr;
#pragma unroll
            for (int nt = 0; nt < 8; nt++) {
                int cc = n0 + wn * 64 + nt * 8 + gc * 2;
                *(float2*)(Cp + (long)r0 * ES + cc) =
                    make_float2(acc[mt][nt][0], acc[mt][nt][1]);
                *(float2*)(Cp + (long)(r0 + 8) * ES + cc) =
                    make_float2(acc[mt][nt][2], acc[mt][nt][3]);
            }
        }
    }
}

// fused QKV+rope: grid.z encodes proj in [0,3) and layer in [0,3)
__global__ __launch_bounds__(256, 2) void tf32_gemm_qkv(
    const float* __restrict__ x,
    const float* __restrict__ Wq, const float* __restrict__ Wk,
    const float* __restrict__ Wv,
    float* __restrict__ qb, float* __restrict__ kb, float* __restrict__ vt,
    const float* __restrict__ cosb, const float* __restrict__ sinb)
{
    extern __shared__ char smem[];
    const int z = blockIdx.z;
    const int proj  = z % 3;
    const int layer = z / 3;
    const float* W = (proj == 0 ? Wq : (proj == 1 ? Wk : Wv)) +
                     (long)layer * ES * ES;
    float* C = (proj == 0 ? qb : (proj == 1 ? kb : vt)) +
               (long)layer * LAYER_ELEMS;
    gemm_core(x, W, C, cosb, sinb, proj == 2 ? 2 : 1, smem);
}

__global__ __launch_bounds__(256, 2) void tf32_gemm_single(
    const float* __restrict__ A, const float* __restrict__ W,
    float* __restrict__ C)
{
    extern __shared__ char smem[];
    gemm_core(A, W, C, nullptr, nullptr, 0, smem);
}

// =============================================================================
// Flash attention on tensor cores.
// Block = 128 thr (4 warps), one (qt, h, z) tile of 64 queries.
// S = QK^T in 3xTF32 (Q,K split hi/lo at smem load), PV in 1x tf32.
// Smem: Qh,Ql,Kh,Kl,VsT,Ps each [64][68] fp32.
// =============================================================================
#define ASTR 68
#define AQH  0
#define AQL  (64*ASTR)
#define AKH  (2*64*ASTR)
#define AKL  (3*64*ASTR)
#define AVT  (4*64*ASTR)
#define APS  (5*64*ASTR)
#define ATT_SMEM (6*64*ASTR*4)       // 104448 bytes

__global__ __launch_bounds__(128) void flash_attn_mma(
    const float* __restrict__ Q, const float* __restrict__ K,
    const float* __restrict__ Vt, float* __restrict__ O)
{
    extern __shared__ float sm[];
    const int qt = (int)(gridDim.x - 1 - blockIdx.x);  // big tiles first
    const int h  = blockIdx.y;
    const int z  = blockIdx.z;
    const long baseqk = (long)z * (LS * (long)ES);
    const int lay = z >> 1, bbi = z & 1;
    const long basev = ((long)lay * ES + h * DH) * (long)MROWS + bbi * LS;

    const int tid  = threadIdx.x;
    const int warp = tid >> 5, lane = tid & 31;
    const int gr = lane >> 2, gc = lane & 3;
    const int a_row_in = (lane & 7) + ((lane >> 3) & 1) * 8;
    const int a_koff   = (lane >> 4) * 4;
    const int b_n_in   = (lane & 7) + (lane >> 4) * 8;
    const int b_koff   = ((lane >> 3) & 1) * 4;

    const uint32_t sb = (uint32_t)__cvta_generic_to_shared(sm);

    // ---- load Q once: scale, split hi/lo tf32 ----
#pragma unroll
    for (int i = 0; i < 8; i++) {
        int idx = tid + i * 128;
        int row = idx >> 4, d4 = (idx & 15) << 2;
        float4 v = *(const float4*)(Q + baseqk + (long)(qt * 64 + row) * ES +
                                    h * DH + d4);
        v.x *= ATT_SCALE; v.y *= ATT_SCALE; v.z *= ATT_SCALE; v.w *= ATT_SCALE;
        float4 hi, lo;
        hi.x = tf32r(v.x); lo.x = tf32r(v.x - hi.x);
        hi.y = tf32r(v.y); lo.y = tf32r(v.y - hi.y);
        hi.z = tf32r(v.z); lo.z = tf32r(v.z - hi.z);
        hi.w = tf32r(v.w); lo.w = tf32r(v.w - hi.w);
        *(float4*)(sm + AQH + row * ASTR + d4) = hi;
        *(float4*)(sm + AQL + row * ASTR + d4) = lo;
    }

    float o[8][4];
#pragma unroll
    for (int nt = 0; nt < 8; nt++)
#pragma unroll
        for (int c = 0; c < 4; c++) o[nt][c] = 0.f;
    float m0 = -1e30f, m1 = -1e30f, l0 = 0.f, l1 = 0.f;

    const uint32_t qhB = sb + (uint32_t)((AQH + (warp * 16 + a_row_in) * ASTR + a_koff) * 4);
    const uint32_t qlB = sb + (uint32_t)((AQL + (warp * 16 + a_row_in) * ASTR + a_koff) * 4);
    const uint32_t khB = sb + (uint32_t)((AKH + b_n_in * ASTR + b_koff) * 4);
    const uint32_t klB = sb + (uint32_t)((AKL + b_n_in * ASTR + b_koff) * 4);
    const uint32_t psB = sb + (uint32_t)((APS + (warp * 16 + a_row_in) * ASTR + a_koff) * 4);
    const uint32_t vtB = sb + (uint32_t)((AVT + b_n_in * ASTR + b_koff) * 4);

    for (int kt = 0; kt <= qt; kt++) {
        __syncthreads();   // prev tile fully consumed before overwrite (also Q first iter)
#pragma unroll
        for (int i = 0; i < 8; i++) {
            int idx = tid + i * 128;
            int row = idx >> 4, d4 = (idx & 15) << 2;
            float4 kv = *(const float4*)(K + baseqk + (long)(kt * 64 + row) * ES +
                                         h * DH + d4);
            float4 hi, lo;
            hi.x = tf32r(kv.x); lo.x = tf32r(kv.x - hi.x);
            hi.y = tf32r(kv.y); lo.y = tf32r(kv.y - hi.y);
            hi.z = tf32r(kv.z); lo.z = tf32r(kv.z - hi.z);
            hi.w = tf32r(kv.w); lo.w = tf32r(kv.w - hi.w);
            *(float4*)(sm + AKH + row * ASTR + d4) = hi;
            *(float4*)(sm + AKL + row * ASTR + d4) = lo;
            // V^T tile: row = d, d4 = kv offset (straight copy, pre-cvt)
            float4 vv = *(const float4*)(Vt + basev + (long)row * MROWS +
                                         kt * 64 + d4);
            vv.x = tf32r(vv.x); vv.y = tf32r(vv.y);
            vv.z = tf32r(vv.z); vv.w = tf32r(vv.w);
            *(float4*)(sm + AVT + row * ASTR + d4) = vv;
        }
        __syncthreads();

        // ---- S = Q K^T (3xTF32) ----
        float s[8][4];
#pragma unroll
        for (int nt = 0; nt < 8; nt++)
#pragma unroll
            for (int c = 0; c < 4; c++) s[nt][c] = 0.f;

#pragma unroll
        for (int kk = 0; kk < 8; kk++) {
            uint32_t qh[4], ql[4], kh[8][2], kl[8][2];
            LDSM4(qh[0], qh[1], qh[2], qh[3], qhB + kk * 32);
            LDSM4(ql[0], ql[1], ql[2], ql[3], qlB + kk * 32);
#pragma unroll
            for (int p = 0; p < 4; p++) {
                LDSM4(kh[2*p][0], kh[2*p][1], kh[2*p+1][0], kh[2*p+1][1],
                      khB + p * 16 * ASTR * 4 + kk * 32);
                LDSM4(kl[2*p][0], kl[2*p][1], kl[2*p+1][0], kl[2*p+1][1],
                      klB + p * 16 * ASTR * 4 + kk * 32);
            }
#pragma unroll
            for (int nt = 0; nt < 8; nt++) {
                mma_tf32(s[nt], qh, kh[nt]);
                mma_tf32(s[nt], ql, kh[nt]);
                mma_tf32(s[nt], qh, kl[nt]);
            }
        }

        if (kt == qt) {   // diagonal: causal mask within tile
            int r0 = warp * 16 + gr, r1 = r0 + 8;
#pragma unroll
            for (int nt = 0; nt < 8; nt++) {
                int c0 = nt * 8 + 2 * gc;
                if (c0 > r0)     s[nt][0] = -1e30f;
                if (c0 + 1 > r0) s[nt][1] = -1e30f;
                if (c0 > r1)     s[nt][2] = -1e30f;
                if (c0 + 1 > r1) s[nt][3] = -1e30f;
            }
        }

        // ---- online softmax ----
        float mx0 = -1e30f, mx1 = -1e30f;
#pragma unroll
        for (int nt = 0; nt < 8; nt++) {
            mx0 = fmaxf(mx0, fmaxf(s[nt][0], s[nt][1]));
            mx1 = fmaxf(mx1, fmaxf(s[nt][2], s[nt][3]));
        }
        mx0 = fmaxf(mx0, __shfl_xor_sync(0xffffffffu, mx0, 1));
        mx0 = fmaxf(mx0, __shfl_xor_sync(0xffffffffu, mx0, 2));
        mx1 = fmaxf(mx1, __shfl_xor_sync(0xffffffffu, mx1, 1));
        mx1 = fmaxf(mx1, __shfl_xor_sync(0xffffffffu, mx1, 2));

        float m0n = fmaxf(m0, mx0), m1n = fmaxf(m1, mx1);
        float f0 = __expf(m0 - m0n), f1 = __expf(m1 - m1n);
        m0 = m0n; m1 = m1n;

        float rs0 = 0.f, rs1 = 0.f;
        int pr0 = warp * 16 + gr;
#pragma unroll
        for (int nt = 0; nt < 8; nt++) {
            float p0 = __expf(s[nt][0] - m0n);
            float p1 = __expf(s[nt][1] - m0n);
            float p2 = __expf(s[nt][2] - m1n);
            float p3 = __expf(s[nt][3] - m1n);
            rs0 += p0 + p1; rs1 += p2 + p3;
            *(float2*)(sm + APS + pr0 * ASTR + nt * 8 + 2 * gc) =
                make_float2(tf32r(p0), tf32r(p1));
            *(float2*)(sm + APS + (pr0 + 8) * ASTR + nt * 8 + 2 * gc) =
                make_float2(tf32r(p2), tf32r(p3));
            o[nt][0] *= f0; o[nt][1] *= f0; o[nt][2] *= f1; o[nt][3] *= f1;
        }
        rs0 += __shfl_xor_sync(0xffffffffu, rs0, 1);
        rs0 += __shfl_xor_sync(0xffffffffu, rs0, 2);
        rs1 += __shfl_xor_sync(0xffffffffu, rs1, 1);
        rs1 += __shfl_xor_sync(0xffffffffu, rs1, 2);
        l0 = l0 * f0 + rs0;
        l1 = l1 * f1 + rs1;
        __syncwarp();   // Ps stores visible to own warp's ldmatrix

        // ---- O += P V (1x tf32) ----
#pragma unroll
        for (int kk = 0; kk < 8; kk++) {
            uint32_t pf[4], vf[8][2];
            LDSM4(pf[0], pf[1], pf[2], pf[3], psB + kk * 32);
#pragma unroll
            for (int p = 0; p < 4; p++)
                LDSM4(vf[2*p][0], vf[2*p][1], vf[2*p+1][0], vf[2*p+1][1],
                      vtB + p * 16 * ASTR * 4 + kk * 32);
#pragma unroll
            for (int nt = 0; nt < 8; nt++)
                mma_tf32(o[nt], pf, vf[nt]);
        }
    }

    // ---- epilogue ----
    float i0 = 1.f / l0, i1 = 1.f / l1;
    int r0 = qt * 64 + warp * 16 + gr;
#pragma unroll
    for (int nt = 0; nt < 8; nt++) {
        int cc = h * DH + nt * 8 + 2 * gc;
        *(float2*)(O + baseqk + (long)r0 * ES + cc) =
            make_float2(o[nt][0] * i0, o[nt][1] * i0);
        *(float2*)(O + baseqk + (long)(r0 + 8) * ES + cc) =
            make_float2(o[nt][2] * i1, o[nt][3] * i1);
    }
}

// ---------------- per-row combine -------------------------------------------
__device__ __forceinline__ float blockSum256(float v)
{
    __shared__ float sh[8];
    __shared__ float total;
    int lane = threadIdx.x & 31, warp = threadIdx.x >> 5;
#pragma unroll
    for (int oo = 16; oo; oo >>= 1) v += __shfl_xor_sync(0xffffffffu, v, oo);
    __syncthreads();
    if (lane == 0) sh[warp] = v;
    __syncthreads();
    if (threadIdx.x == 0) {
        float t = 0.f;
#pragma unroll
        for (int i = 0; i < 8; i++) t += sh[i];
        total = t;
    }
    __syncthreads();
    return total;
}

__global__ __launch_bounds__(256) void combine_kernel(
    const float* __restrict__ A,
    const float* __restrict__ x,
    const float* __restrict__ g_ln,
    const float* __restrict__ lambdas,
    const float* __restrict__ g_final,
    const float* __restrict__ alpha,
    float* __restrict__ Y)              // stored tf32-rounded for the Wo GEMM
{
    const int row = blockIdx.x;
    const int tid = threadIdx.x;
    const int e0  = tid * 4;

    float sg0 = 1.f / (1.f + __expf(-lambdas[0]));
    float sg1 = 1.f / (1.f + __expf(-lambdas[1]));
    float sg2 = 1.f / (1.f + __expf(-lambdas[2]));
    float mu  = (sg0 + sg1 + sg2) * (1.f / 3.f);
    float va  = ((sg0 - mu) * (sg0 - mu) + (sg1 - mu) * (sg1 - mu) +
                 (sg2 - mu) * (sg2 - mu)) * (1.f / 3.f);
    float ivs = rsqrtf(va + EPSF);
    float lw0 = (sg0 - mu) * ivs, lw1 = (sg1 - mu) * ivs, lw2 = (sg2 - mu) * ivs;

    long ro = (long)row * ES + e0;
    float4 a0 = *(const float4*)(A + 0L * LAYER_ELEMS + ro);
    float4 a1 = *(const float4*)(A + 1L * LAYER_ELEMS + ro);
    float4 a2 = *(const float4*)(A + 2L * LAYER_ELEMS + ro);
    float4 xv = *(const float4*)(x + ro);

    float ss0 = blockSum256(a0.x*a0.x + a0.y*a0.y + a0.z*a0.z + a0.w*a0.w);
    float ss1 = blockSum256(a1.x*a1.x + a1.y*a1.y + a1.z*a1.z + a1.w*a1.w);
    float ss2 = blockSum256(a2.x*a2.x + a2.y*a2.y + a2.z*a2.z + a2.w*a2.w);

    float r0 = rsqrtf(ss0 * (1.f / ES) + EPSF) * lw0;
    float r1 = rsqrtf(ss1 * (1.f / ES) + EPSF) * lw1;
    float r2 = rsqrtf(ss2 * (1.f / ES) + EPSF) * lw2;
    float al = alpha[0];

    float4 g0 = *(const float4*)(g_ln + 0 * ES + e0);
    float4 g1 = *(const float4*)(g_ln + 1 * ES + e0);
    float4 g2 = *(const float4*)(g_ln + 2 * ES + e0);

    float4 cb;
    cb.x = a0.x*r0*g0.x + a1.x*r1*g1.x + a2.x*r2*g2.x + al*xv.x;
    cb.y = a0.y*r0*g0.y + a1.y*r1*g1.y + a2.y*r2*g2.y + al*xv.y;
    cb.z = a0.z*r0*g0.z + a1.z*r1*g1.z + a2.z*r2*g2.z + al*xv.z;
    cb.w = a0.w*r0*g0.w + a1.w*r1*g1.w + a2.w*r2*g2.w + al*xv.w;

    float ssc = blockSum256(cb.x*cb.x + cb.y*cb.y + cb.z*cb.z + cb.w*cb.w);
    float rc  = rsqrtf(ssc * (1.f / ES) + EPSF);

    float4 gf = *(const float4*)(g_final + e0);
    float4 yv;
    yv.x = tf32r(cb.x * rc * gf.x); yv.y = tf32r(cb.y * rc * gf.y);
    yv.z = tf32r(cb.z * rc * gf.z); yv.w = tf32r(cb.w * rc * gf.w);
    *(float4*)(Y + ro) = yv;
}

// ---------------- launch ------------------------------------------------------
extern "C" void kernel_launch(void* const* d_in, const int* in_sizes, int n_in,
                              void* d_out, int out_size)
{
    const float* x       = (const float*)d_in[0];
    const float* cosb    = (const float*)d_in[1];
    const float* sinb    = (const float*)d_in[2];
    // d_in[3] = attn_mask (pure causal; implemented directly)
    const float* Wq      = (const float*)d_in[4];
    const float* Wk      = (const float*)d_in[5];
    const float* Wv      = (const float*)d_in[6];
    const float* g_ln    = (const float*)d_in[7];
    const float* lambdas = (const float*)d_in[8];
    const float* Wo      = (const float*)d_in[9];
    const float* g_final = (const float*)d_in[10];
    const float* alpha   = (const float*)d_in[11];
    float* out = (float*)d_out;

    float *qb, *kb, *vt, *ab, *yb, *xr, *wqr, *wkr, *wvr, *wor;
    cudaGetSymbolAddress((void**)&qb, d_QB);
    cudaGetSymbolAddress((void**)&kb, d_KB);
    cudaGetSymbolAddress((void**)&vt, d_VT);
    cudaGetSymbolAddress((void**)&ab, d_AB);
    cudaGetSymbolAddress((void**)&yb, d_YB);
    cudaGetSymbolAddress((void**)&xr, d_XR);
    cudaGetSymbolAddress((void**)&wqr, d_WQR);
    cudaGetSymbolAddress((void**)&wkr, d_WKR);
    cudaGetSymbolAddress((void**)&wvr, d_WVR);
    cudaGetSymbolAddress((void**)&wor, d_WOR);

    cudaFuncSetAttribute(tf32_gemm_qkv,
                         cudaFuncAttributeMaxDynamicSharedMemorySize, GEMM_SMEM);
    cudaFuncSetAttribute(tf32_gemm_single,
                         cudaFuncAttributeMaxDynamicSharedMemorySize, GEMM_SMEM);
    cudaFuncSetAttribute(flash_attn_mma,
                         cudaFuncAttributeMaxDynamicSharedMemorySize, ATT_SMEM);

    // 0) pre-round GEMM inputs to tf32-valued fp32 (hoists cvt out of mainloop)
    const int WEL = NLAY * ES * ES;   // 3145728
    preround_kernel<<<(LAYER_ELEMS / 4 + 255) / 256, 256>>>(x,  xr,  LAYER_ELEMS / 4);
    preround_kernel<<<(WEL / 4 + 255) / 256, 256>>>(Wq, wqr, WEL / 4);
    preround_kernel<<<(WEL / 4 + 255) / 256, 256>>>(Wk, wkr, WEL / 4);
    preround_kernel<<<(WEL / 4 + 255) / 256, 256>>>(Wv, wvr, WEL / 4);
    preround_kernel<<<(ES * ES / 4 + 255) / 256, 256>>>(Wo, wor, ES * ES / 4);

    // 1) fused QKV projections (+RoPE on Q/K, transposed store for V)
    dim3 gqkv(ES / TBN, MROWS / TBM, 9);
    tf32_gemm_qkv<<<gqkv, 256, GEMM_SMEM>>>(xr, wqr, wkr, wvr, qb, kb, vt,
                                            cosb, sinb);

    // 2) tensor-core flash attention
    flash_attn_mma<<<dim3(LS / 64, HH, NLAY * BB), 128, ATT_SMEM>>>(qb, kb, vt, ab);

    // 3) per-row norms + lambda combine + residual + final rmsnorm (tf32 out)
    combine_kernel<<<MROWS, 256>>>(ab, x, g_ln, lambdas, g_final, alpha, yb);

    // 4) output projection
    tf32_gemm_single<<<dim3(ES / TBN, MROWS / TBM, 1), 256, GEMM_SMEM>>>(
        yb, wor, out);
}

// round 16
// speedup vs baseline: 4.8451x; 1.3373x over previous
#include <cuda_runtime.h>
#include <cuda_fp16.h>
#include <cstdint>

// Problem constants
#define NLAY 3
#define BB   2
#define LS   1024
#define ES   1024
#define HH   16
#define DH   64
#define MROWS (BB*LS)              // 2048
#define LAYER_ELEMS (BB*LS*ES)     // 2097152
#define ATT_SCALE 0.125f           // D^-0.5 = 1/8
#define EPSF 1e-5f

// ---------------- scratch (static device allocations; no cudaMalloc) --------
__device__ float  d_QB[NLAY * LAYER_ELEMS];
__device__ float  d_KB[NLAY * LAYER_ELEMS];
__device__ float  d_VT[NLAY * LAYER_ELEMS];  // V transposed: [lay][E][B*L]
__device__ float  d_AB[NLAY * LAYER_ELEMS];
__device__ __half d_YH[LAYER_ELEMS];         // combine output (fp16 for Wo GEMM)
// fp16 copies of GEMM inputs
__device__ __half d_XH[LAYER_ELEMS];
__device__ __half d_WQH[NLAY * ES * ES];
__device__ __half d_WKH[NLAY * ES * ES];
__device__ __half d_WVH[NLAY * ES * ES];
__device__ __half d_WOH[ES * ES];

// =============================================================================
// mma helpers
// =============================================================================
__device__ __forceinline__ uint32_t f2tf32_u(uint32_t bits) {
    uint32_t u;
    asm("cvt.rna.tf32.f32 %0, %1;" : "=r"(u) : "f"(__uint_as_float(bits)));
    return u;
}
__device__ __forceinline__ float tf32r(float x) {
    return __uint_as_float(f2tf32_u(__float_as_uint(x)));
}

__device__ __forceinline__ void mma_tf32(
    float c[4], const uint32_t a[4], const uint32_t b[2])
{
    asm volatile(
        "mma.sync.aligned.m16n8k8.row.col.f32.tf32.tf32.f32 "
        "{%0,%1,%2,%3}, {%4,%5,%6,%7}, {%8,%9}, {%0,%1,%2,%3};"
        : "+f"(c[0]), "+f"(c[1]), "+f"(c[2]), "+f"(c[3])
        : "r"(a[0]), "r"(a[1]), "r"(a[2]), "r"(a[3]),
          "r"(b[0]), "r"(b[1]));
}

__device__ __forceinline__ void mma_f16(
    float c[4], const uint32_t a[4], const uint32_t b[2])
{
    asm volatile(
        "mma.sync.aligned.m16n8k16.row.col.f32.f16.f16.f32 "
        "{%0,%1,%2,%3}, {%4,%5,%6,%7}, {%8,%9}, {%0,%1,%2,%3};"
        : "+f"(c[0]), "+f"(c[1]), "+f"(c[2]), "+f"(c[3])
        : "r"(a[0]), "r"(a[1]), "r"(a[2]), "r"(a[3]),
          "r"(b[0]), "r"(b[1]));
}

__device__ __forceinline__ void cp16(uint32_t dst, const void* src) {
    asm volatile("cp.async.cg.shared.global [%0], [%1], 16;" :: "r"(dst), "l"(src));
}
__device__ __forceinline__ void cp_commit() {
    asm volatile("cp.async.commit_group;");
}
__device__ __forceinline__ void cp_wait0() {
    asm volatile("cp.async.wait_group 0;");
}

#define LDSM4(r0, r1, r2, r3, addr) \
    asm volatile("ldmatrix.sync.aligned.m8n8.x4.shared.b16 {%0,%1,%2,%3}, [%4];" \
                 : "=r"(r0), "=r"(r1), "=r"(r2), "=r"(r3) : "r"(addr))

// ---------------- fused fp32 -> fp16 convert for all GEMM inputs -------------
__global__ void convert_fp16_all(
    const float* __restrict__ x,  const float* __restrict__ wq,
    const float* __restrict__ wk, const float* __restrict__ wv,
    const float* __restrict__ wo,
    __half* __restrict__ xh,  __half* __restrict__ wqh,
    __half* __restrict__ wkh, __half* __restrict__ wvh,
    __half* __restrict__ woh)
{
    const int N0 = LAYER_ELEMS / 4;        // x: 524288 float4s
    const int NW = (NLAY * ES * ES) / 4;   // each W: 786432
    const int NO = (ES * ES) / 4;          // Wo: 262144
    int i = blockIdx.x * blockDim.x + threadIdx.x;
    const float* s; __half* d; int j;
    if (i < N0)               { s = x;  d = xh;  j = i; }
    else if (i < N0 + NW)     { s = wq; d = wqh; j = i - N0; }
    else if (i < N0 + 2 * NW) { s = wk; d = wkh; j = i - N0 - NW; }
    else if (i < N0 + 3 * NW) { s = wv; d = wvh; j = i - N0 - 2 * NW; }
    else { j = i - N0 - 3 * NW; if (j >= NO) return; s = wo; d = woh; }
    float4 v = ((const float4*)s)[j];
    ((__half2*)d)[j * 2]     = __floats2half2_rn(v.x, v.y);
    ((__half2*)d)[j * 2 + 1] = __floats2half2_rn(v.z, v.w);
}

// =============================================================================
// FP16 tensor-core GEMM: C = A @ W^T (fp32 accum).
// Blocktile 128x128, K-tile 64 halves (128B rows, byte-identical layout to the
// validated tf32 version: 144B smem row stride, 16B chunks). 8 warps, warptile
// 32x64, m16n8k16. mode 0 = plain, 1 = fused RoPE, 2 = transposed store (Vt).
// =============================================================================
#define TBM 128
#define TBN 128
#define TBKH 64                       // K halves per tile
#define SH 72                         // smem row stride in halves (144 B)
#define TILE_B (TBM * SH * 2)         // bytes per matrix tile (18432)
#define BUF_B  (2 * TILE_B)           // A+B per stage (36864)
#define GEMM_SMEM (2 * BUF_B)         // 73728 bytes

__device__ __forceinline__ void gemm_core(
    const __half* __restrict__ A, const __half* __restrict__ W,
    float* __restrict__ Cp,
    const float* __restrict__ cosb, const float* __restrict__ sinb,
    int mode, char* smem)
{
    const int tid  = threadIdx.x;
    const int m0   = blockIdx.y * TBM;
    const int n0   = blockIdx.x * TBN;
    const int warp = tid >> 5, lane = tid & 31;
    const int wm = warp & 3;
    const int wn = warp >> 2;
    const int gr = lane >> 2;
    const int gc = lane & 3;

    const uint32_t sbase = (uint32_t)__cvta_generic_to_shared(smem);

    // ldmatrix thread source mapping (same 16B-chunk structure as tf32 ver)
    const int a_row_in = (lane & 7) + ((lane >> 3) & 1) * 8;   // 0..15
    const int a_kb     = (lane >> 4) * 16;                     // 0 or 16 bytes
    const int b_n_in   = (lane & 7) + (lane >> 4) * 8;         // 0..15
    const int b_kb     = ((lane >> 3) & 1) * 16;               // 0 or 16 bytes

    // cp.async mapping: 128 rows x 8 chunks of 16B per matrix, 4 per thread
    const int crow = tid >> 3;        // 0..31 (+i*32)
    const int cch  = (tid & 7) * 8;   // halves offset 0..56

    float acc[2][8][4];
#pragma unroll
    for (int mt = 0; mt < 2; mt++)
#pragma unroll
        for (int nt = 0; nt < 8; nt++)
#pragma unroll
            for (int c = 0; c < 4; c++) acc[mt][nt][c] = 0.f;

    const int KT = ES / TBKH;         // 16

    {
#pragma unroll
        for (int i = 0; i < 4; i++) {
            int r = crow + i * 32;
            uint32_t da = sbase + (uint32_t)((r * SH + cch) * 2);
            uint32_t db = sbase + (uint32_t)(TILE_B + (r * SH + cch) * 2);
            cp16(da, A + (long)(m0 + r) * ES + cch);
            cp16(db, W + (long)(n0 + r) * ES + cch);
        }
        cp_commit();
    }

    for (int kt = 0; kt < KT; kt++) {
        cp_wait0();
        __syncthreads();

        if (kt + 1 < KT) {
            const int k0 = (kt + 1) * TBKH;
            const uint32_t boff = (uint32_t)(((kt + 1) & 1) * BUF_B);
#pragma unroll
            for (int i = 0; i < 4; i++) {
                int r = crow + i * 32;
                uint32_t da = sbase + boff + (uint32_t)((r * SH + cch) * 2);
                uint32_t db = sbase + boff + (uint32_t)(TILE_B + (r * SH + cch) * 2);
                cp16(da, A + (long)(m0 + r) * ES + k0 + cch);
                cp16(db, W + (long)(n0 + r) * ES + k0 + cch);
            }
            cp_commit();
        }

        const uint32_t off = (uint32_t)((kt & 1) * BUF_B);
        const uint32_t aB = sbase + off +
            (uint32_t)((wm * 32 + a_row_in) * SH * 2 + a_kb);
        const uint32_t bB = sbase + off + TILE_B +
            (uint32_t)((wn * 64 + b_n_in) * SH * 2 + b_kb);

#pragma unroll
        for (int kk = 0; kk < 4; kk++) {   // 4 x k16 substeps over 64 halves
            uint32_t af[2][4], bf[8][2];
            LDSM4(af[0][0], af[0][1], af[0][2], af[0][3], aB + kk * 32);
            LDSM4(af[1][0], af[1][1], af[1][2], af[1][3],
                  aB + 16 * SH * 2 + kk * 32);
#pragma unroll
            for (int p = 0; p < 4; p++)
                LDSM4(bf[2 * p][0], bf[2 * p][1], bf[2 * p + 1][0], bf[2 * p + 1][1],
                      bB + p * 16 * SH * 2 + kk * 32);

#pragma unroll
            for (int mt = 0; mt < 2; mt++)
#pragma unroll
                for (int nt = 0; nt < 8; nt++)
                    mma_f16(acc[mt][nt], af[mt], bf[nt]);
        }
        __syncthreads();
    }

    // ---- epilogue ----
    if (mode == 1) {
        // fused RoPE (rotate_half): pair (d, d+32) lives in (nt, nt+4)
#pragma unroll
        for (int mt = 0; mt < 2; mt++) {
            int r0g = m0 + wm * 32 + mt * 16 + gr;
            int l0 = r0g & (LS - 1);
            int l1 = (r0g + 8) & (LS - 1);
#pragma unroll
            for (int nt = 0; nt < 4; nt++) {
                int d = nt * 8 + gc * 2;
                float2 c0  = *(const float2*)(cosb + l0 * DH + d);
                float2 s0  = *(const float2*)(sinb + l0 * DH + d);
                float2 c0h = *(const float2*)(cosb + l0 * DH + d + 32);
                float2 s0h = *(const float2*)(sinb + l0 * DH + d + 32);
                float2 c1  = *(const float2*)(cosb + l1 * DH + d);
                float2 s1  = *(const float2*)(sinb + l1 * DH + d);
                float2 c1h = *(const float2*)(cosb + l1 * DH + d + 32);
                float2 s1h = *(const float2*)(sinb + l1 * DH + d + 32);

                const float* x1 = acc[mt][nt];
                const float* x2 = acc[mt][nt + 4];
                int cc = n0 + wn * 64 + nt * 8 + gc * 2;
                *(float2*)(Cp + (long)r0g * ES + cc) =
                    make_float2(x1[0] * c0.x - x2[0] * s0.x,
                                x1[1] * c0.y - x2[1] * s0.y);
                *(float2*)(Cp + (long)r0g * ES + cc + 32) =
                    make_float2(x2[0] * c0h.x + x1[0] * s0h.x,
                                x2[1] * c0h.y + x1[1] * s0h.y);
                *(float2*)(Cp + (long)(r0g + 8) * ES + cc) =
                    make_float2(x1[2] * c1.x - x2[2] * s1.x,
                                x1[3] * c1.y - x2[3] * s1.y);
                *(float2*)(Cp + (long)(r0g + 8) * ES + cc + 32) =
                    make_float2(x2[2] * c1h.x + x1[2] * s1h.x,
                                x2[3] * c1h.y + x1[3] * s1h.y);
            }
        }
    } else if (mode == 2) {
        // transposed store: Vt[col][row], row-length MROWS
#pragma unroll
        for (int mt = 0; mt < 2; mt++) {
            int r0 = m0 + wm * 32 + mt * 16 + gr;
#pragma unroll
            for (int nt = 0; nt < 8; nt++) {
                int cc = n0 + wn * 64 + nt * 8 + gc * 2;
                Cp[(long)cc * MROWS + r0]           = acc[mt][nt][0];
                Cp[(long)(cc + 1) * MROWS + r0]     = acc[mt][nt][1];
                Cp[(long)cc * MROWS + r0 + 8]       = acc[mt][nt][2];
                Cp[(long)(cc + 1) * MROWS + r0 + 8] = acc[mt][nt][3];
            }
        }
    } else {
#pragma unroll
        for (int mt = 0; mt < 2; mt++) {
            int r0 = m0 + wm * 32 + mt * 16 + gr;
#pragma unroll
            for (int nt = 0; nt < 8; nt++) {
                int cc = n0 + wn * 64 + nt * 8 + gc * 2;
                *(float2*)(Cp + (long)r0 * ES + cc) =
                    make_float2(acc[mt][nt][0], acc[mt][nt][1]);
                *(float2*)(Cp + (long)(r0 + 8) * ES + cc) =
                    make_float2(acc[mt][nt][2], acc[mt][nt][3]);
            }
        }
    }
}

// fused QKV+rope: grid.z encodes proj in [0,3) and layer in [0,3)
__global__ __launch_bounds__(256, 2) void f16_gemm_qkv(
    const __half* __restrict__ x,
    const __half* __restrict__ Wq, const __half* __restrict__ Wk,
    const __half* __restrict__ Wv,
    float* __restrict__ qb, float* __restrict__ kb, float* __restrict__ vt,
    const float* __restrict__ cosb, const float* __restrict__ sinb)
{
    extern __shared__ char smem[];
    const int z = blockIdx.z;
    const int proj  = z % 3;
    const int layer = z / 3;
    const __half* W = (proj == 0 ? Wq : (proj == 1 ? Wk : Wv)) +
                      (long)layer * ES * ES;
    float* C = (proj == 0 ? qb : (proj == 1 ? kb : vt)) +
               (long)layer * LAYER_ELEMS;
    gemm_core(x, W, C, cosb, sinb, proj == 2 ? 2 : 1, smem);
}

__global__ __launch_bounds__(256, 2) void f16_gemm_single(
    const __half* __restrict__ A, const __half* __restrict__ W,
    float* __restrict__ C)
{
    extern __shared__ char smem[];
    gemm_core(A, W, C, nullptr, nullptr, 0, smem);
}

// =============================================================================
// Flash attention on tensor cores (unchanged from round 12/14).
// Block = 128 thr (4 warps), one (qt, h, z) tile of 64 queries.
// S = QK^T in 3xTF32 (Q,K split hi/lo at smem load), PV in 1x tf32.
// =============================================================================
#define ASTR 68
#define AQH  0
#define AQL  (64*ASTR)
#define AKH  (2*64*ASTR)
#define AKL  (3*64*ASTR)
#define AVT  (4*64*ASTR)
#define APS  (5*64*ASTR)
#define ATT_SMEM (6*64*ASTR*4)       // 104448 bytes

__global__ __launch_bounds__(128) void flash_attn_mma(
    const float* __restrict__ Q, const float* __restrict__ K,
    const float* __restrict__ Vt, float* __restrict__ O)
{
    extern __shared__ float sm[];
    const int qt = (int)(gridDim.x - 1 - blockIdx.x);  // big tiles first
    const int h  = blockIdx.y;
    const int z  = blockIdx.z;
    const long baseqk = (long)z * (LS * (long)ES);
    const int lay = z >> 1, bbi = z & 1;
    const long basev = ((long)lay * ES + h * DH) * (long)MROWS + bbi * LS;

    const int tid  = threadIdx.x;
    const int warp = tid >> 5, lane = tid & 31;
    const int gr = lane >> 2, gc = lane & 3;
    const int a_row_in = (lane & 7) + ((lane >> 3) & 1) * 8;
    const int a_koff   = (lane >> 4) * 4;
    const int b_n_in   = (lane & 7) + (lane >> 4) * 8;
    const int b_koff   = ((lane >> 3) & 1) * 4;

    const uint32_t sb = (uint32_t)__cvta_generic_to_shared(sm);

    // ---- load Q once: scale, split hi/lo tf32 ----
#pragma unroll
    for (int i = 0; i < 8; i++) {
        int idx = tid + i * 128;
        int row = idx >> 4, d4 = (idx & 15) << 2;
        float4 v = *(const float4*)(Q + baseqk + (long)(qt * 64 + row) * ES +
                                    h * DH + d4);
        v.x *= ATT_SCALE; v.y *= ATT_SCALE; v.z *= ATT_SCALE; v.w *= ATT_SCALE;
        float4 hi, lo;
        hi.x = tf32r(v.x); lo.x = tf32r(v.x - hi.x);
        hi.y = tf32r(v.y); lo.y = tf32r(v.y - hi.y);
        hi.z = tf32r(v.z); lo.z = tf32r(v.z - hi.z);
        hi.w = tf32r(v.w); lo.w = tf32r(v.w - hi.w);
        *(float4*)(sm + AQH + row * ASTR + d4) = hi;
        *(float4*)(sm + AQL + row * ASTR + d4) = lo;
    }

    float o[8][4];
#pragma unroll
    for (int nt = 0; nt < 8; nt++)
#pragma unroll
        for (int c = 0; c < 4; c++) o[nt][c] = 0.f;
    float m0 = -1e30f, m1 = -1e30f, l0 = 0.f, l1 = 0.f;

    const uint32_t qhB = sb + (uint32_t)((AQH + (warp * 16 + a_row_in) * ASTR + a_koff) * 4);
    const uint32_t qlB = sb + (uint32_t)((AQL + (warp * 16 + a_row_in) * ASTR + a_koff) * 4);
    const uint32_t khB = sb + (uint32_t)((AKH + b_n_in * ASTR + b_koff) * 4);
    const uint32_t klB = sb + (uint32_t)((AKL + b_n_in * ASTR + b_koff) * 4);
    const uint32_t psB = sb + (uint32_t)((APS + (warp * 16 + a_row_in) * ASTR + a_koff) * 4);
    const uint32_t vtB = sb + (uint32_t)((AVT + b_n_in * ASTR + b_koff) * 4);

    for (int kt = 0; kt <= qt; kt++) {
        __syncthreads();
#pragma unroll
        for (int i = 0; i < 8; i++) {
            int idx = tid + i * 128;
            int row = idx >> 4, d4 = (idx & 15) << 2;
            float4 kv = *(const float4*)(K + baseqk + (long)(kt * 64 + row) * ES +
                                         h * DH + d4);
            float4 hi, lo;
            hi.x = tf32r(kv.x); lo.x = tf32r(kv.x - hi.x);
            hi.y = tf32r(kv.y); lo.y = tf32r(kv.y - hi.y);
            hi.z = tf32r(kv.z); lo.z = tf32r(kv.z - hi.z);
            hi.w = tf32r(kv.w); lo.w = tf32r(kv.w - hi.w);
            *(float4*)(sm + AKH + row * ASTR + d4) = hi;
            *(float4*)(sm + AKL + row * ASTR + d4) = lo;
            float4 vv = *(const float4*)(Vt + basev + (long)row * MROWS +
                                         kt * 64 + d4);
            vv.x = tf32r(vv.x); vv.y = tf32r(vv.y);
            vv.z = tf32r(vv.z); vv.w = tf32r(vv.w);
            *(float4*)(sm + AVT + row * ASTR + d4) = vv;
        }
        __syncthreads();

        // ---- S = Q K^T (3xTF32) ----
        float s[8][4];
#pragma unroll
        for (int nt = 0; nt < 8; nt++)
#pragma unroll
            for (int c = 0; c < 4; c++) s[nt][c] = 0.f;

#pragma unroll
        for (int kk = 0; kk < 8; kk++) {
            uint32_t qh[4], ql[4], kh[8][2], kl[8][2];
            LDSM4(qh[0], qh[1], qh[2], qh[3], qhB + kk * 32);
            LDSM4(ql[0], ql[1], ql[2], ql[3], qlB + kk * 32);
#pragma unroll
            for (int p = 0; p < 4; p++) {
                LDSM4(kh[2*p][0], kh[2*p][1], kh[2*p+1][0], kh[2*p+1][1],
                      khB + p * 16 * ASTR * 4 + kk * 32);
                LDSM4(kl[2*p][0], kl[2*p][1], kl[2*p+1][0], kl[2*p+1][1],
                      klB + p * 16 * ASTR * 4 + kk * 32);
            }
#pragma unroll
            for (int nt = 0; nt < 8; nt++) {
                mma_tf32(s[nt], qh, kh[nt]);
                mma_tf32(s[nt], ql, kh[nt]);
                mma_tf32(s[nt], qh, kl[nt]);
            }
        }

        if (kt == qt) {   // diagonal: causal mask within tile
            int r0 = warp * 16 + gr, r1 = r0 + 8;
#pragma unroll
            for (int nt = 0; nt < 8; nt++) {
                int c0 = nt * 8 + 2 * gc;
                if (c0 > r0)     s[nt][0] = -1e30f;
                if (c0 + 1 > r0) s[nt][1] = -1e30f;
                if (c0 > r1)     s[nt][2] = -1e30f;
                if (c0 + 1 > r1) s[nt][3] = -1e30f;
            }
        }

        // ---- online softmax ----
        float mx0 = -1e30f, mx1 = -1e30f;
#pragma unroll
        for (int nt = 0; nt < 8; nt++) {
            mx0 = fmaxf(mx0, fmaxf(s[nt][0], s[nt][1]));
            mx1 = fmaxf(mx1, fmaxf(s[nt][2], s[nt][3]));
        }
        mx0 = fmaxf(mx0, __shfl_xor_sync(0xffffffffu, mx0, 1));
        mx0 = fmaxf(mx0, __shfl_xor_sync(0xffffffffu, mx0, 2));
        mx1 = fmaxf(mx1, __shfl_xor_sync(0xffffffffu, mx1, 1));
        mx1 = fmaxf(mx1, __shfl_xor_sync(0xffffffffu, mx1, 2));

        float m0n = fmaxf(m0, mx0), m1n = fmaxf(m1, mx1);
        float f0 = __expf(m0 - m0n), f1 = __expf(m1 - m1n);
        m0 = m0n; m1 = m1n;

        float rs0 = 0.f, rs1 = 0.f;
        int pr0 = warp * 16 + gr;
#pragma unroll
        for (int nt = 0; nt < 8; nt++) {
            float p0 = __expf(s[nt][0] - m0n);
            float p1 = __expf(s[nt][1] - m0n);
            float p2 = __expf(s[nt][2] - m1n);
            float p3 = __expf(s[nt][3] - m1n);
            rs0 += p0 + p1; rs1 += p2 + p3;
            *(float2*)(sm + APS + pr0 * ASTR + nt * 8 + 2 * gc) =
                make_float2(tf32r(p0), tf32r(p1));
            *(float2*)(sm + APS + (pr0 + 8) * ASTR + nt * 8 + 2 * gc) =
                make_float2(tf32r(p2), tf32r(p3));
            o[nt][0] *= f0; o[nt][1] *= f0; o[nt][2] *= f1; o[nt][3] *= f1;
        }
        rs0 += __shfl_xor_sync(0xffffffffu, rs0, 1);
        rs0 += __shfl_xor_sync(0xffffffffu, rs0, 2);
        rs1 += __shfl_xor_sync(0xffffffffu, rs1, 1);
        rs1 += __shfl_xor_sync(0xffffffffu, rs1, 2);
        l0 = l0 * f0 + rs0;
        l1 = l1 * f1 + rs1;
        __syncwarp();

        // ---- O += P V (1x tf32) ----
#pragma unroll
        for (int kk = 0; kk < 8; kk++) {
            uint32_t pf[4], vf[8][2];
            LDSM4(pf[0], pf[1], pf[2], pf[3], psB + kk * 32);
#pragma unroll
            for (int p = 0; p < 4; p++)
                LDSM4(vf[2*p][0], vf[2*p][1], vf[2*p+1][0], vf[2*p+1][1],
                      vtB + p * 16 * ASTR * 4 + kk * 32);
#pragma unroll
            for (int nt = 0; nt < 8; nt++)
                mma_tf32(o[nt], pf, vf[nt]);
        }
    }

    // ---- epilogue ----
    float i0 = 1.f / l0, i1 = 1.f / l1;
    int r0 = qt * 64 + warp * 16 + gr;
#pragma unroll
    for (int nt = 0; nt < 8; nt++) {
        int cc = h * DH + nt * 8 + 2 * gc;
        *(float2*)(O + baseqk + (long)r0 * ES + cc) =
            make_float2(o[nt][0] * i0, o[nt][1] * i0);
        *(float2*)(O + baseqk + (long)(r0 + 8) * ES + cc) =
            make_float2(o[nt][2] * i1, o[nt][3] * i1);
    }
}

// ---------------- per-row combine (emits fp16 for the Wo GEMM) ---------------
__device__ __forceinline__ float blockSum256(float v)
{
    __shared__ float sh[8];
    __shared__ float total;
    int lane = threadIdx.x & 31, warp = threadIdx.x >> 5;
#pragma unroll
    for (int oo = 16; oo; oo >>= 1) v += __shfl_xor_sync(0xffffffffu, v, oo);
    __syncthreads();
    if (lane == 0) sh[warp] = v;
    __syncthreads();
    if (threadIdx.x == 0) {
        float t = 0.f;
#pragma unroll
        for (int i = 0; i < 8; i++) t += sh[i];
        total = t;
    }
    __syncthreads();
    return total;
}

__global__ __launch_bounds__(256) void combine_kernel(
    const float* __restrict__ A,
    const float* __restrict__ x,
    const float* __restrict__ g_ln,
    const float* __restrict__ lambdas,
    const float* __restrict__ g_final,
    const float* __restrict__ alpha,
    __half* __restrict__ Y)
{
    const int row = blockIdx.x;
    const int tid = threadIdx.x;
    const int e0  = tid * 4;

    float sg0 = 1.f / (1.f + __expf(-lambdas[0]));
    float sg1 = 1.f / (1.f + __expf(-lambdas[1]));
    float sg2 = 1.f / (1.f + __expf(-lambdas[2]));
    float mu  = (sg0 + sg1 + sg2) * (1.f / 3.f);
    float va  = ((sg0 - mu) * (sg0 - mu) + (sg1 - mu) * (sg1 - mu) +
                 (sg2 - mu) * (sg2 - mu)) * (1.f / 3.f);
    float ivs = rsqrtf(va + EPSF);
    float lw0 = (sg0 - mu) * ivs, lw1 = (sg1 - mu) * ivs, lw2 = (sg2 - mu) * ivs;

    long ro = (long)row * ES + e0;
    float4 a0 = *(const float4*)(A + 0L * LAYER_ELEMS + ro);
    float4 a1 = *(const float4*)(A + 1L * LAYER_ELEMS + ro);
    float4 a2 = *(const float4*)(A + 2L * LAYER_ELEMS + ro);
    float4 xv = *(const float4*)(x + ro);

    float ss0 = blockSum256(a0.x*a0.x + a0.y*a0.y + a0.z*a0.z + a0.w*a0.w);
    float ss1 = blockSum256(a1.x*a1.x + a1.y*a1.y + a1.z*a1.z + a1.w*a1.w);
    float ss2 = blockSum256(a2.x*a2.x + a2.y*a2.y + a2.z*a2.z + a2.w*a2.w);

    float r0 = rsqrtf(ss0 * (1.f / ES) + EPSF) * lw0;
    float r1 = rsqrtf(ss1 * (1.f / ES) + EPSF) * lw1;
    float r2 = rsqrtf(ss2 * (1.f / ES) + EPSF) * lw2;
    float al = alpha[0];

    float4 g0 = *(const float4*)(g_ln + 0 * ES + e0);
    float4 g1 = *(const float4*)(g_ln + 1 * ES + e0);
    float4 g2 = *(const float4*)(g_ln + 2 * ES + e0);

    float4 cb;
    cb.x = a0.x*r0*g0.x + a1.x*r1*g1.x + a2.x*r2*g2.x + al*xv.x;
    cb.y = a0.y*r0*g0.y + a1.y*r1*g1.y + a2.y*r2*g2.y + al*xv.y;
    cb.z = a0.z*r0*g0.z + a1.z*r1*g1.z + a2.z*r2*g2.z + al*xv.z;
    cb.w = a0.w*r0*g0.w + a1.w*r1*g1.w + a2.w*r2*g2.w + al*xv.w;

    float ssc = blockSum256(cb.x*cb.x + cb.y*cb.y + cb.z*cb.z + cb.w*cb.w);
    float rc  = rsqrtf(ssc * (1.f / ES) + EPSF);

    float4 gf = *(const float4*)(g_final + e0);
    __half2* yp = (__half2*)(Y + ro);
    yp[0] = __floats2half2_rn(cb.x * rc * gf.x, cb.y * rc * gf.y);
    yp[1] = __floats2half2_rn(cb.z * rc * gf.z, cb.w * rc * gf.w);
}

// ---------------- launch ------------------------------------------------------
extern "C" void kernel_launch(void* const* d_in, const int* in_sizes, int n_in,
                              void* d_out, int out_size)
{
    const float* x       = (const float*)d_in[0];
    const float* cosb    = (const float*)d_in[1];
    const float* sinb    = (const float*)d_in[2];
    // d_in[3] = attn_mask (pure causal; implemented directly)
    const float* Wq      = (const float*)d_in[4];
    const float* Wk      = (const float*)d_in[5];
    const float* Wv      = (const float*)d_in[6];
    const float* g_ln    = (const float*)d_in[7];
    const float* lambdas = (const float*)d_in[8];
    const float* Wo      = (const float*)d_in[9];
    const float* g_final = (const float*)d_in[10];
    const float* alpha   = (const float*)d_in[11];
    float* out = (float*)d_out;

    float *qb, *kb, *vt, *ab;
    __half *yh, *xh, *wqh, *wkh, *wvh, *woh;
    cudaGetSymbolAddress((void**)&qb,  d_QB);
    cudaGetSymbolAddress((void**)&kb,  d_KB);
    cudaGetSymbolAddress((void**)&vt,  d_VT);
    cudaGetSymbolAddress((void**)&ab,  d_AB);
    cudaGetSymbolAddress((void**)&yh,  d_YH);
    cudaGetSymbolAddress((void**)&xh,  d_XH);
    cudaGetSymbolAddress((void**)&wqh, d_WQH);
    cudaGetSymbolAddress((void**)&wkh, d_WKH);
    cudaGetSymbolAddress((void**)&wvh, d_WVH);
    cudaGetSymbolAddress((void**)&woh, d_WOH);

    cudaFuncSetAttribute(f16_gemm_qkv,
                         cudaFuncAttributeMaxDynamicSharedMemorySize, GEMM_SMEM);
    cudaFuncSetAttribute(f16_gemm_single,
                         cudaFuncAttributeMaxDynamicSharedMemorySize, GEMM_SMEM);
    cudaFuncSetAttribute(flash_attn_mma,
                         cudaFuncAttributeMaxDynamicSharedMemorySize, ATT_SMEM);

    // 0) one fused fp32 -> fp16 convert of all GEMM inputs
    const int CONV_TOTAL = LAYER_ELEMS / 4 + 3 * (NLAY * ES * ES) / 4 +
                           (ES * ES) / 4;                      // 3145728
    convert_fp16_all<<<(CONV_TOTAL + 255) / 256, 256>>>(
        x, Wq, Wk, Wv, Wo, xh, wqh, wkh, wvh, woh);

    // 1) fused QKV projections (+RoPE on Q/K, transposed store for V), fp16 mma
    dim3 gqkv(ES / TBN, MROWS / TBM, 9);
    f16_gemm_qkv<<<gqkv, 256, GEMM_SMEM>>>(xh, wqh, wkh, wvh, qb, kb, vt,
                                           cosb, sinb);

    // 2) tensor-core flash attention (tf32, unchanged)
    flash_attn_mma<<<dim3(LS / 64, HH, NLAY * BB), 128, ATT_SMEM>>>(qb, kb, vt, ab);

    // 3) per-row norms + lambda combine + residual + final rmsnorm (fp16 out)
    combine_kernel<<<MROWS, 256>>>(ab, x, g_ln, lambdas, g_final, alpha, yh);

    // 4) output projection (fp16 mma)
    f16_gemm_single<<<dim3(ES / TBN, MROWS / TBM, 1), 256, GEMM_SMEM>>>(
        yh, woh, out);
}

// round 17
// speedup vs baseline: 6.2066x; 1.2810x over previous
#include <cuda_runtime.h>
#include <cuda_fp16.h>
#include <cstdint>

// Problem constants
#define NLAY 3
#define BB   2
#define LS   1024
#define ES   1024
#define HH   16
#define DH   64
#define MROWS (BB*LS)              // 2048
#define LAYER_ELEMS (BB*LS*ES)     // 2097152
#define ATT_SCALE 0.125f           // D^-0.5 = 1/8
#define EPSF 1e-5f

// ---------------- scratch (static device allocations; no cudaMalloc) --------
__device__ __half d_QHI[NLAY * LAYER_ELEMS];  // Q rope'd+scaled, hi plane
__device__ __half d_QLO[NLAY * LAYER_ELEMS];  // Q residual lo plane
__device__ __half d_KHI[NLAY * LAYER_ELEMS];
__device__ __half d_KLO[NLAY * LAYER_ELEMS];
__device__ __half d_VTH[NLAY * LAYER_ELEMS];  // V transposed fp16: [lay][E][B*L]
__device__ float  d_AB[NLAY * LAYER_ELEMS];   // attention out (fp32)
__device__ __half d_YH[LAYER_ELEMS];          // combine out (fp16 for Wo GEMM)
// fp16 copies of GEMM inputs
__device__ __half d_XH[LAYER_ELEMS];
__device__ __half d_WQH[NLAY * ES * ES];
__device__ __half d_WKH[NLAY * ES * ES];
__device__ __half d_WVH[NLAY * ES * ES];
__device__ __half d_WOH[ES * ES];

// =============================================================================
// mma helpers
// =============================================================================
__device__ __forceinline__ void mma_f16(
    float c[4], const uint32_t a[4], const uint32_t b[2])
{
    asm volatile(
        "mma.sync.aligned.m16n8k16.row.col.f32.f16.f16.f32 "
        "{%0,%1,%2,%3}, {%4,%5,%6,%7}, {%8,%9}, {%0,%1,%2,%3};"
        : "+f"(c[0]), "+f"(c[1]), "+f"(c[2]), "+f"(c[3])
        : "r"(a[0]), "r"(a[1]), "r"(a[2]), "r"(a[3]),
          "r"(b[0]), "r"(b[1]));
}

__device__ __forceinline__ void cp16(uint32_t dst, const void* src) {
    asm volatile("cp.async.cg.shared.global [%0], [%1], 16;" :: "r"(dst), "l"(src));
}
__device__ __forceinline__ void cp_commit() {
    asm volatile("cp.async.commit_group;");
}
__device__ __forceinline__ void cp_wait0() {
    asm volatile("cp.async.wait_group 0;");
}

#define LDSM4(r0, r1, r2, r3, addr) \
    asm volatile("ldmatrix.sync.aligned.m8n8.x4.shared.b16 {%0,%1,%2,%3}, [%4];" \
                 : "=r"(r0), "=r"(r1), "=r"(r2), "=r"(r3) : "r"(addr))

// hi/lo fp16 split of an fp32 value
__device__ __forceinline__ void hl_split(float v, __half& hi, __half& lo) {
    hi = __float2half_rn(v);
    lo = __float2half_rn(v - __half2float(hi));
}

// ---------------- fused fp32 -> fp16 convert for all GEMM inputs -------------
__global__ void convert_fp16_all(
    const float* __restrict__ x,  const float* __restrict__ wq,
    const float* __restrict__ wk, const float* __restrict__ wv,
    const float* __restrict__ wo,
    __half* __restrict__ xh,  __half* __restrict__ wqh,
    __half* __restrict__ wkh, __half* __restrict__ wvh,
    __half* __restrict__ woh)
{
    const int N0 = LAYER_ELEMS / 4;
    const int NW = (NLAY * ES * ES) / 4;
    const int NO = (ES * ES) / 4;
    int i = blockIdx.x * blockDim.x + threadIdx.x;
    const float* s; __half* d; int j;
    if (i < N0)               { s = x;  d = xh;  j = i; }
    else if (i < N0 + NW)     { s = wq; d = wqh; j = i - N0; }
    else if (i < N0 + 2 * NW) { s = wk; d = wkh; j = i - N0 - NW; }
    else if (i < N0 + 3 * NW) { s = wv; d = wvh; j = i - N0 - 2 * NW; }
    else { j = i - N0 - 3 * NW; if (j >= NO) return; s = wo; d = woh; }
    float4 v = ((const float4*)s)[j];
    ((__half2*)d)[j * 2]     = __floats2half2_rn(v.x, v.y);
    ((__half2*)d)[j * 2 + 1] = __floats2half2_rn(v.z, v.w);
}

// =============================================================================
// FP16 tensor-core GEMM: C = A @ W^T (fp32 accum). Blocktile 128x128, K-tile 64
// halves, 8 warps (4M x 2N), m16n8k16, cp.async double buffer.
// mode 0: fp32 plain store. mode 1: RoPE*scale then hi/lo fp16 split to two
// planes. mode 2: transposed fp16 store (Vt[col][row]).
// =============================================================================
#define TBM 128
#define TBN 128
#define TBKH 64
#define SH 72                         // smem row stride in halves (144 B)
#define TILE_B (TBM * SH * 2)         // 18432 B
#define BUF_B  (2 * TILE_B)           // 36864 B
#define GEMM_SMEM (2 * BUF_B)         // 73728 B

__device__ __forceinline__ void gemm_core(
    const __half* __restrict__ A, const __half* __restrict__ W,
    void* out0, void* out1, float scale,
    const float* __restrict__ cosb, const float* __restrict__ sinb,
    int mode, char* smem)
{
    const int tid  = threadIdx.x;
    const int m0   = blockIdx.y * TBM;
    const int n0   = blockIdx.x * TBN;
    const int warp = tid >> 5, lane = tid & 31;
    const int wm = warp & 3;
    const int wn = warp >> 2;
    const int gr = lane >> 2;
    const int gc = lane & 3;

    const uint32_t sbase = (uint32_t)__cvta_generic_to_shared(smem);

    const int a_row_in = (lane & 7) + ((lane >> 3) & 1) * 8;
    const int a_kb     = (lane >> 4) * 16;
    const int b_n_in   = (lane & 7) + (lane >> 4) * 8;
    const int b_kb     = ((lane >> 3) & 1) * 16;

    const int crow = tid >> 3;
    const int cch  = (tid & 7) * 8;

    float acc[2][8][4];
#pragma unroll
    for (int mt = 0; mt < 2; mt++)
#pragma unroll
        for (int nt = 0; nt < 8; nt++)
#pragma unroll
            for (int c = 0; c < 4; c++) acc[mt][nt][c] = 0.f;

    const int KT = ES / TBKH;         // 16

    {
#pragma unroll
        for (int i = 0; i < 4; i++) {
            int r = crow + i * 32;
            uint32_t da = sbase + (uint32_t)((r * SH + cch) * 2);
            uint32_t db = sbase + (uint32_t)(TILE_B + (r * SH + cch) * 2);
            cp16(da, A + (long)(m0 + r) * ES + cch);
            cp16(db, W + (long)(n0 + r) * ES + cch);
        }
        cp_commit();
    }

    for (int kt = 0; kt < KT; kt++) {
        cp_wait0();
        __syncthreads();

        if (kt + 1 < KT) {
            const int k0 = (kt + 1) * TBKH;
            const uint32_t boff = (uint32_t)(((kt + 1) & 1) * BUF_B);
#pragma unroll
            for (int i = 0; i < 4; i++) {
                int r = crow + i * 32;
                uint32_t da = sbase + boff + (uint32_t)((r * SH + cch) * 2);
                uint32_t db = sbase + boff + (uint32_t)(TILE_B + (r * SH + cch) * 2);
                cp16(da, A + (long)(m0 + r) * ES + k0 + cch);
                cp16(db, W + (long)(n0 + r) * ES + k0 + cch);
            }
            cp_commit();
        }

        const uint32_t off = (uint32_t)((kt & 1) * BUF_B);
        const uint32_t aB = sbase + off +
            (uint32_t)((wm * 32 + a_row_in) * SH * 2 + a_kb);
        const uint32_t bB = sbase + off + TILE_B +
            (uint32_t)((wn * 64 + b_n_in) * SH * 2 + b_kb);

#pragma unroll
        for (int kk = 0; kk < 4; kk++) {
            uint32_t af[2][4], bf[8][2];
            LDSM4(af[0][0], af[0][1], af[0][2], af[0][3], aB + kk * 32);
            LDSM4(af[1][0], af[1][1], af[1][2], af[1][3],
                  aB + 16 * SH * 2 + kk * 32);
#pragma unroll
            for (int p = 0; p < 4; p++)
                LDSM4(bf[2 * p][0], bf[2 * p][1], bf[2 * p + 1][0], bf[2 * p + 1][1],
                      bB + p * 16 * SH * 2 + kk * 32);

#pragma unroll
            for (int mt = 0; mt < 2; mt++)
#pragma unroll
                for (int nt = 0; nt < 8; nt++)
                    mma_f16(acc[mt][nt], af[mt], bf[nt]);
        }
        __syncthreads();
    }

    // ---- epilogue ----
    if (mode == 1) {
        __half* Hp = (__half*)out0;
        __half* Lp = (__half*)out1;
#pragma unroll
        for (int mt = 0; mt < 2; mt++) {
            int r0g = m0 + wm * 32 + mt * 16 + gr;
            int l0 = r0g & (LS - 1);
            int l1 = (r0g + 8) & (LS - 1);
#pragma unroll
            for (int nt = 0; nt < 4; nt++) {
                int d = nt * 8 + gc * 2;
                float2 c0  = *(const float2*)(cosb + l0 * DH + d);
                float2 s0  = *(const float2*)(sinb + l0 * DH + d);
                float2 c0h = *(const float2*)(cosb + l0 * DH + d + 32);
                float2 s0h = *(const float2*)(sinb + l0 * DH + d + 32);
                float2 c1  = *(const float2*)(cosb + l1 * DH + d);
                float2 s1  = *(const float2*)(sinb + l1 * DH + d);
                float2 c1h = *(const float2*)(cosb + l1 * DH + d + 32);
                float2 s1h = *(const float2*)(sinb + l1 * DH + d + 32);

                const float* x1 = acc[mt][nt];
                const float* x2 = acc[mt][nt + 4];
                int cc = n0 + wn * 64 + nt * 8 + gc * 2;

                float v00 = (x1[0] * c0.x - x2[0] * s0.x) * scale;
                float v01 = (x1[1] * c0.y - x2[1] * s0.y) * scale;
                float w00 = (x2[0] * c0h.x + x1[0] * s0h.x) * scale;
                float w01 = (x2[1] * c0h.y + x1[1] * s0h.y) * scale;
                float v10 = (x1[2] * c1.x - x2[2] * s1.x) * scale;
                float v11 = (x1[3] * c1.y - x2[3] * s1.y) * scale;
                float w10 = (x2[2] * c1h.x + x1[2] * s1h.x) * scale;
                float w11 = (x2[3] * c1h.y + x1[3] * s1h.y) * scale;

                __half h0, h1, lo0, lo1;
                long o00 = (long)r0g * ES + cc;
                hl_split(v00, h0, lo0); hl_split(v01, h1, lo1);
                *(__half2*)(Hp + o00) = __halves2half2(h0, h1);
                *(__half2*)(Lp + o00) = __halves2half2(lo0, lo1);
                hl_split(w00, h0, lo0); hl_split(w01, h1, lo1);
                *(__half2*)(Hp + o00 + 32) = __halves2half2(h0, h1);
                *(__half2*)(Lp + o00 + 32) = __halves2half2(lo0, lo1);
                long o10 = (long)(r0g + 8) * ES + cc;
                hl_split(v10, h0, lo0); hl_split(v11, h1, lo1);
                *(__half2*)(Hp + o10) = __halves2half2(h0, h1);
                *(__half2*)(Lp + o10) = __halves2half2(lo0, lo1);
                hl_split(w10, h0, lo0); hl_split(w11, h1, lo1);
                *(__half2*)(Hp + o10 + 32) = __halves2half2(h0, h1);
                *(__half2*)(Lp + o10 + 32) = __halves2half2(lo0, lo1);
            }
        }
    } else if (mode == 2) {
        __half* Vp = (__half*)out0;
#pragma unroll
        for (int mt = 0; mt < 2; mt++) {
            int r0 = m0 + wm * 32 + mt * 16 + gr;
#pragma unroll
            for (int nt = 0; nt < 8; nt++) {
                int cc = n0 + wn * 64 + nt * 8 + gc * 2;
                Vp[(long)cc * MROWS + r0]           = __float2half_rn(acc[mt][nt][0]);
                Vp[(long)(cc + 1) * MROWS + r0]     = __float2half_rn(acc[mt][nt][1]);
                Vp[(long)cc * MROWS + r0 + 8]       = __float2half_rn(acc[mt][nt][2]);
                Vp[(long)(cc + 1) * MROWS + r0 + 8] = __float2half_rn(acc[mt][nt][3]);
            }
        }
    } else {
        float* Cp = (float*)out0;
#pragma unroll
        for (int mt = 0; mt < 2; mt++) {
            int r0 = m0 + wm * 32 + mt * 16 + gr;
#pragma unroll
            for (int nt = 0; nt < 8; nt++) {
                int cc = n0 + wn * 64 + nt * 8 + gc * 2;
                *(float2*)(Cp + (long)r0 * ES + cc) =
                    make_float2(acc[mt][nt][0], acc[mt][nt][1]);
                *(float2*)(Cp + (long)(r0 + 8) * ES + cc) =
                    make_float2(acc[mt][nt][2], acc[mt][nt][3]);
            }
        }
    }
}

// fused QKV: grid.z encodes proj in [0,3) and layer in [0,3)
__global__ __launch_bounds__(256, 2) void f16_gemm_qkv(
    const __half* __restrict__ x,
    const __half* __restrict__ Wq, const __half* __restrict__ Wk,
    const __half* __restrict__ Wv,
    __half* __restrict__ qhi, __half* __restrict__ qlo,
    __half* __restrict__ khi, __half* __restrict__ klo,
    __half* __restrict__ vth,
    const float* __restrict__ cosb, const float* __restrict__ sinb)
{
    extern __shared__ char smem[];
    const int z = blockIdx.z;
    const int proj  = z % 3;
    const int layer = z / 3;
    const long loff = (long)layer * LAYER_ELEMS;
    const __half* W = (proj == 0 ? Wq : (proj == 1 ? Wk : Wv)) +
                      (long)layer * ES * ES;
    if (proj == 0)
        gemm_core(x, W, qhi + loff, qlo + loff, ATT_SCALE, cosb, sinb, 1, smem);
    else if (proj == 1)
        gemm_core(x, W, khi + loff, klo + loff, 1.0f, cosb, sinb, 1, smem);
    else
        gemm_core(x, W, vth + loff, nullptr, 1.0f, nullptr, nullptr, 2, smem);
}

__global__ __launch_bounds__(256, 2) void f16_gemm_single(
    const __half* __restrict__ A, const __half* __restrict__ W,
    float* __restrict__ C)
{
    extern __shared__ char smem[];
    gemm_core(A, W, C, nullptr, 1.0f, nullptr, nullptr, 0, smem);
}

// =============================================================================
// FP16 flash attention. Block = 128 thr (4 warps), one (qt,h,z) 64-query tile.
// S = Qh*Kh + Ql*Kh + Qh*Kl (m16n8k16 fp16, fp32 accum) — ~fp32 scores.
// PV in 1x fp16 (same eps as tf32). All smem fp16, 144B row stride.
// =============================================================================
#define SHH 72
#define AQH  0
#define AQL  (64*SHH)
#define AKH  (2*64*SHH)
#define AKL  (3*64*SHH)
#define AVT  (4*64*SHH)
#define APS  (5*64*SHH)
#define ATT_SMEM (6*64*SHH*2)        // 55296 bytes

__global__ __launch_bounds__(128) void flash_attn_f16(
    const __half* __restrict__ Qh, const __half* __restrict__ Ql,
    const __half* __restrict__ Kh, const __half* __restrict__ Kl,
    const __half* __restrict__ Vt, float* __restrict__ O)
{
    extern __shared__ __half smh[];
    const int qt = (int)(gridDim.x - 1 - blockIdx.x);  // big tiles first
    const int h  = blockIdx.y;
    const int z  = blockIdx.z;
    const long baseqk = (long)z * (LS * (long)ES);
    const int lay = z >> 1, bbi = z & 1;
    const long basev = ((long)lay * ES + h * DH) * (long)MROWS + bbi * LS;

    const int tid  = threadIdx.x;
    const int warp = tid >> 5, lane = tid & 31;
    const int gr = lane >> 2, gc = lane & 3;
    const int a_row_in = (lane & 7) + ((lane >> 3) & 1) * 8;
    const int a_kb     = (lane >> 4) * 16;
    const int b_n_in   = (lane & 7) + (lane >> 4) * 8;
    const int b_kb     = ((lane >> 3) & 1) * 16;

    const uint32_t sb = (uint32_t)__cvta_generic_to_shared(smh);

    // ---- load Q hi/lo once (pure 16B copies) ----
#pragma unroll
    for (int i = 0; i < 4; i++) {
        int idx = tid + i * 128;
        int row = idx >> 3, ch = (idx & 7) * 8;
        long g = baseqk + (long)(qt * 64 + row) * ES + h * DH + ch;
        *(int4*)(smh + AQH + row * SHH + ch) = *(const int4*)(Qh + g);
        *(int4*)(smh + AQL + row * SHH + ch) = *(const int4*)(Ql + g);
    }

    float o[8][4];
#pragma unroll
    for (int nt = 0; nt < 8; nt++)
#pragma unroll
        for (int c = 0; c < 4; c++) o[nt][c] = 0.f;
    float m0 = -1e30f, m1 = -1e30f, l0 = 0.f, l1 = 0.f;

    const uint32_t qhB = sb + (uint32_t)((AQH + (warp * 16 + a_row_in) * SHH) * 2 + a_kb);
    const uint32_t qlB = sb + (uint32_t)((AQL + (warp * 16 + a_row_in) * SHH) * 2 + a_kb);
    const uint32_t khB = sb + (uint32_t)((AKH + b_n_in * SHH) * 2 + b_kb);
    const uint32_t klB = sb + (uint32_t)((AKL + b_n_in * SHH) * 2 + b_kb);
    const uint32_t psB = sb + (uint32_t)((APS + (warp * 16 + a_row_in) * SHH) * 2 + a_kb);
    const uint32_t vtB = sb + (uint32_t)((AVT + b_n_in * SHH) * 2 + b_kb);

    for (int kt = 0; kt <= qt; kt++) {
        __syncthreads();   // prev tile fully consumed before overwrite
#pragma unroll
        for (int i = 0; i < 4; i++) {
            int idx = tid + i * 128;
            int row = idx >> 3, ch = (idx & 7) * 8;
            long g = baseqk + (long)(kt * 64 + row) * ES + h * DH + ch;
            *(int4*)(smh + AKH + row * SHH + ch) = *(const int4*)(Kh + g);
            *(int4*)(smh + AKL + row * SHH + ch) = *(const int4*)(Kl + g);
            *(int4*)(smh + AVT + row * SHH + ch) =
                *(const int4*)(Vt + basev + (long)row * MROWS + kt * 64 + ch);
        }
        __syncthreads();

        // ---- S = Q K^T (hi/lo fp16, 3 mma per nt per k16) ----
        float s[8][4];
#pragma unroll
        for (int nt = 0; nt < 8; nt++)
#pragma unroll
            for (int c = 0; c < 4; c++) s[nt][c] = 0.f;

#pragma unroll
        for (int kk = 0; kk < 4; kk++) {
            uint32_t qhf[4], qlf[4], khf[8][2], klf[8][2];
            LDSM4(qhf[0], qhf[1], qhf[2], qhf[3], qhB + kk * 32);
            LDSM4(qlf[0], qlf[1], qlf[2], qlf[3], qlB + kk * 32);
#pragma unroll
            for (int p = 0; p < 4; p++) {
                LDSM4(khf[2*p][0], khf[2*p][1], khf[2*p+1][0], khf[2*p+1][1],
                      khB + p * 16 * SHH * 2 + kk * 32);
                LDSM4(klf[2*p][0], klf[2*p][1], klf[2*p+1][0], klf[2*p+1][1],
                      klB + p * 16 * SHH * 2 + kk * 32);
            }
#pragma unroll
            for (int nt = 0; nt < 8; nt++) {
                mma_f16(s[nt], qhf, khf[nt]);
                mma_f16(s[nt], qlf, khf[nt]);
                mma_f16(s[nt], qhf, klf[nt]);
            }
        }

        if (kt == qt) {   // diagonal: causal mask within tile
            int r0 = warp * 16 + gr, r1 = r0 + 8;
#pragma unroll
            for (int nt = 0; nt < 8; nt++) {
                int c0 = nt * 8 + 2 * gc;
                if (c0 > r0)     s[nt][0] = -1e30f;
                if (c0 + 1 > r0) s[nt][1] = -1e30f;
                if (c0 > r1)     s[nt][2] = -1e30f;
                if (c0 + 1 > r1) s[nt][3] = -1e30f;
            }
        }

        // ---- online softmax ----
        float mx0 = -1e30f, mx1 = -1e30f;
#pragma unroll
        for (int nt = 0; nt < 8; nt++) {
            mx0 = fmaxf(mx0, fmaxf(s[nt][0], s[nt][1]));
            mx1 = fmaxf(mx1, fmaxf(s[nt][2], s[nt][3]));
        }
        mx0 = fmaxf(mx0, __shfl_xor_sync(0xffffffffu, mx0, 1));
        mx0 = fmaxf(mx0, __shfl_xor_sync(0xffffffffu, mx0, 2));
        mx1 = fmaxf(mx1, __shfl_xor_sync(0xffffffffu, mx1, 1));
        mx1 = fmaxf(mx1, __shfl_xor_sync(0xffffffffu, mx1, 2));

        float m0n = fmaxf(m0, mx0), m1n = fmaxf(m1, mx1);
        float f0 = __expf(m0 - m0n), f1 = __expf(m1 - m1n);
        m0 = m0n; m1 = m1n;

        float rs0 = 0.f, rs1 = 0.f;
        int pr0 = warp * 16 + gr;
#pragma unroll
        for (int nt = 0; nt < 8; nt++) {
            float p0 = __expf(s[nt][0] - m0n);
            float p1 = __expf(s[nt][1] - m0n);
            float p2 = __expf(s[nt][2] - m1n);
            float p3 = __expf(s[nt][3] - m1n);
            rs0 += p0 + p1; rs1 += p2 + p3;
            *(__half2*)(smh + APS + pr0 * SHH + nt * 8 + 2 * gc) =
                __floats2half2_rn(p0, p1);
            *(__half2*)(smh + APS + (pr0 + 8) * SHH + nt * 8 + 2 * gc) =
                __floats2half2_rn(p2, p3);
            o[nt][0] *= f0; o[nt][1] *= f0; o[nt][2] *= f1; o[nt][3] *= f1;
        }
        rs0 += __shfl_xor_sync(0xffffffffu, rs0, 1);
        rs0 += __shfl_xor_sync(0xffffffffu, rs0, 2);
        rs1 += __shfl_xor_sync(0xffffffffu, rs1, 1);
        rs1 += __shfl_xor_sync(0xffffffffu, rs1, 2);
        l0 = l0 * f0 + rs0;
        l1 = l1 * f1 + rs1;
        __syncwarp();   // Ps stores visible to own warp's ldmatrix

        // ---- O += P V (1x fp16) ----
#pragma unroll
        for (int kk = 0; kk < 4; kk++) {
            uint32_t pf[4], vf[8][2];
            LDSM4(pf[0], pf[1], pf[2], pf[3], psB + kk * 32);
#pragma unroll
            for (int p = 0; p < 4; p++)
                LDSM4(vf[2*p][0], vf[2*p][1], vf[2*p+1][0], vf[2*p+1][1],
                      vtB + p * 16 * SHH * 2 + kk * 32);
#pragma unroll
            for (int nt = 0; nt < 8; nt++)
                mma_f16(o[nt], pf, vf[nt]);
        }
    }

    // ---- epilogue ----
    float i0 = 1.f / l0, i1 = 1.f / l1;
    int r0 = qt * 64 + warp * 16 + gr;
#pragma unroll
    for (int nt = 0; nt < 8; nt++) {
        int cc = h * DH + nt * 8 + 2 * gc;
        *(float2*)(O + baseqk + (long)r0 * ES + cc) =
            make_float2(o[nt][0] * i0, o[nt][1] * i0);
        *(float2*)(O + baseqk + (long)(r0 + 8) * ES + cc) =
            make_float2(o[nt][2] * i1, o[nt][3] * i1);
    }
}

// ---------------- per-row combine (emits fp16 for the Wo GEMM) ---------------
__device__ __forceinline__ float blockSum256(float v)
{
    __shared__ float sh[8];
    __shared__ float total;
    int lane = threadIdx.x & 31, warp = threadIdx.x >> 5;
#pragma unroll
    for (int oo = 16; oo; oo >>= 1) v += __shfl_xor_sync(0xffffffffu, v, oo);
    __syncthreads();
    if (lane == 0) sh[warp] = v;
    __syncthreads();
    if (threadIdx.x == 0) {
        float t = 0.f;
#pragma unroll
        for (int i = 0; i < 8; i++) t += sh[i];
        total = t;
    }
    __syncthreads();
    return total;
}

__global__ __launch_bounds__(256) void combine_kernel(
    const float* __restrict__ A,
    const float* __restrict__ x,
    const float* __restrict__ g_ln,
    const float* __restrict__ lambdas,
    const float* __restrict__ g_final,
    const float* __restrict__ alpha,
    __half* __restrict__ Y)
{
    const int row = blockIdx.x;
    const int tid = threadIdx.x;
    const int e0  = tid * 4;

    float sg0 = 1.f / (1.f + __expf(-lambdas[0]));
    float sg1 = 1.f / (1.f + __expf(-lambdas[1]));
    float sg2 = 1.f / (1.f + __expf(-lambdas[2]));
    float mu  = (sg0 + sg1 + sg2) * (1.f / 3.f);
    float va  = ((sg0 - mu) * (sg0 - mu) + (sg1 - mu) * (sg1 - mu) +
                 (sg2 - mu) * (sg2 - mu)) * (1.f / 3.f);
    float ivs = rsqrtf(va + EPSF);
    float lw0 = (sg0 - mu) * ivs, lw1 = (sg1 - mu) * ivs, lw2 = (sg2 - mu) * ivs;

    long ro = (long)row * ES + e0;
    float4 a0 = *(const float4*)(A + 0L * LAYER_ELEMS + ro);
    float4 a1 = *(const float4*)(A + 1L * LAYER_ELEMS + ro);
    float4 a2 = *(const float4*)(A + 2L * LAYER_ELEMS + ro);
    float4 xv = *(const float4*)(x + ro);

    float ss0 = blockSum256(a0.x*a0.x + a0.y*a0.y + a0.z*a0.z + a0.w*a0.w);
    float ss1 = blockSum256(a1.x*a1.x + a1.y*a1.y + a1.z*a1.z + a1.w*a1.w);
    float ss2 = blockSum256(a2.x*a2.x + a2.y*a2.y + a2.z*a2.z + a2.w*a2.w);

    float r0 = rsqrtf(ss0 * (1.f / ES) + EPSF) * lw0;
    float r1 = rsqrtf(ss1 * (1.f / ES) + EPSF) * lw1;
    float r2 = rsqrtf(ss2 * (1.f / ES) + EPSF) * lw2;
    float al = alpha[0];

    float4 g0 = *(const float4*)(g_ln + 0 * ES + e0);
    float4 g1 = *(const float4*)(g_ln + 1 * ES + e0);
    float4 g2 = *(const float4*)(g_ln + 2 * ES + e0);

    float4 cb;
    cb.x = a0.x*r0*g0.x + a1.x*r1*g1.x + a2.x*r2*g2.x + al*xv.x;
    cb.y = a0.y*r0*g0.y + a1.y*r1*g1.y + a2.y*r2*g2.y + al*xv.y;
    cb.z = a0.z*r0*g0.z + a1.z*r1*g1.z + a2.z*r2*g2.z + al*xv.z;
    cb.w = a0.w*r0*g0.w + a1.w*r1*g1.w + a2.w*r2*g2.w + al*xv.w;

    float ssc = blockSum256(cb.x*cb.x + cb.y*cb.y + cb.z*cb.z + cb.w*cb.w);
    float rc  = rsqrtf(ssc * (1.f / ES) + EPSF);

    float4 gf = *(const float4*)(g_final + e0);
    __half2* yp = (__half2*)(Y + ro);
    yp[0] = __floats2half2_rn(cb.x * rc * gf.x, cb.y * rc * gf.y);
    yp[1] = __floats2half2_rn(cb.z * rc * gf.z, cb.w * rc * gf.w);
}

// ---------------- launch ------------------------------------------------------
extern "C" void kernel_launch(void* const* d_in, const int* in_sizes, int n_in,
                              void* d_out, int out_size)
{
    const float* x       = (const float*)d_in[0];
    const float* cosb    = (const float*)d_in[1];
    const float* sinb    = (const float*)d_in[2];
    // d_in[3] = attn_mask (pure causal; implemented directly)
    const float* Wq      = (const float*)d_in[4];
    const float* Wk      = (const float*)d_in[5];
    const float* Wv      = (const float*)d_in[6];
    const float* g_ln    = (const float*)d_in[7];
    const float* lambdas = (const float*)d_in[8];
    const float* Wo      = (const float*)d_in[9];
    const float* g_final = (const float*)d_in[10];
    const float* alpha   = (const float*)d_in[11];
    float* out = (float*)d_out;

    float *ab;
    __half *qhi, *qlo, *khi, *klo, *vth, *yh, *xh, *wqh, *wkh, *wvh, *woh;
    cudaGetSymbolAddress((void**)&qhi, d_QHI);
    cudaGetSymbolAddress((void**)&qlo, d_QLO);
    cudaGetSymbolAddress((void**)&khi, d_KHI);
    cudaGetSymbolAddress((void**)&klo, d_KLO);
    cudaGetSymbolAddress((void**)&vth, d_VTH);
    cudaGetSymbolAddress((void**)&ab,  d_AB);
    cudaGetSymbolAddress((void**)&yh,  d_YH);
    cudaGetSymbolAddress((void**)&xh,  d_XH);
    cudaGetSymbolAddress((void**)&wqh, d_WQH);
    cudaGetSymbolAddress((void**)&wkh, d_WKH);
    cudaGetSymbolAddress((void**)&wvh, d_WVH);
    cudaGetSymbolAddress((void**)&woh, d_WOH);

    cudaFuncSetAttribute(f16_gemm_qkv,
                         cudaFuncAttributeMaxDynamicSharedMemorySize, GEMM_SMEM);
    cudaFuncSetAttribute(f16_gemm_single,
                         cudaFuncAttributeMaxDynamicSharedMemorySize, GEMM_SMEM);
    cudaFuncSetAttribute(flash_attn_f16,
                         cudaFuncAttributeMaxDynamicSharedMemorySize, ATT_SMEM);

    // 0) one fused fp32 -> fp16 convert of all GEMM inputs
    const int CONV_TOTAL = LAYER_ELEMS / 4 + 3 * (NLAY * ES * ES) / 4 +
                           (ES * ES) / 4;
    convert_fp16_all<<<(CONV_TOTAL + 255) / 256, 256>>>(
        x, Wq, Wk, Wv, Wo, xh, wqh, wkh, wvh, woh);

    // 1) fused QKV projections: RoPE+scale+hi/lo split for Q/K, fp16 Vt
    dim3 gqkv(ES / TBN, MROWS / TBM, 9);
    f16_gemm_qkv<<<gqkv, 256, GEMM_SMEM>>>(xh, wqh, wkh, wvh,
                                           qhi, qlo, khi, klo, vth, cosb, sinb);

    // 2) fp16 flash attention
    flash_attn_f16<<<dim3(LS / 64, HH, NLAY * BB), 128, ATT_SMEM>>>(
        qhi, qlo, khi, klo, vth, ab);

    // 3) per-row norms + lambda combine + residual + final rmsnorm (fp16 out)
    combine_kernel<<<MROWS, 256>>>(ab, x, g_ln, lambdas, g_final, alpha, yh);

    // 4) output projection (fp16 mma)
    f16_gemm_single<<<dim3(ES / TBN, MROWS / TBM, 1), 256, GEMM_SMEM>>>(
        yh, woh, out);
}